// round 6
// baseline (speedup 1.0000x reference)
#include <cuda_runtime.h>
#include <math.h>

#define BB 512
#define SS 256
#define ID 12
#define HH 256
#define AA 9
#define G4 1024   // 4*HH

// -------- scratch (static device allocations; no runtime alloc) --------
static __device__ float g_seq[(size_t)BB * SS * HH];   // emb, then reused as y0
static __device__ float g_xg[(size_t)BB * SS * G4];    // precomputed input gates, cols gc = j*4+gate
static __device__ float g_hbuf[2][BB * HH];            // ping-pong hidden state
static __device__ float g_cbuf[BB * HH];               // cell state

__device__ __forceinline__ float sigm(float x) { return 1.f / (1.f + expf(-x)); }

// -------- zero h/c before each layer --------
__global__ void zero_hc_kernel() {
    int i = blockIdx.x * blockDim.x + threadIdx.x;
    if (i < BB * HH) { g_hbuf[0][i] = 0.f; g_cbuf[i] = 0.f; }
}

// -------- emb = relu(x @ W_emb^T + b_emb), x:[B*S,12], W:[256,12] --------
__global__ void emb_kernel(const float* __restrict__ x,
                           const float* __restrict__ W,
                           const float* __restrict__ bias) {
    __shared__ float ws[HH * ID];      // 12 KB
    __shared__ float xs[8][ID];
    int tid = threadIdx.x;
    for (int i = tid; i < HH * ID; i += 256) ws[i] = W[i];
    size_t row0 = (size_t)blockIdx.x * 8;
    if (tid < 8 * ID) xs[tid / ID][tid % ID] = x[row0 * ID + tid];
    __syncthreads();
    float b = bias[tid];
#pragma unroll
    for (int r = 0; r < 8; r++) {
        float acc = b;
#pragma unroll
        for (int i = 0; i < ID; i++) acc = fmaf(xs[r][i], ws[tid * ID + i], acc);
        g_seq[(row0 + r) * HH + tid] = fmaxf(acc, 0.f);
    }
}

// -------- xg[M,1024] = g_seq[M,256] @ w_ih^T  + (b_ih+b_hh), permuted cols --------
// output col gc -> weight row wr = (gc&3)*256 + (gc>>2)
// 128x128 tile, BK=16, 256 threads, 8x8 micro-tile (split 4+4)
__global__ void xg_gemm(const float* __restrict__ wih,
                        const float* __restrict__ bih,
                        const float* __restrict__ bhh) {
    __shared__ float a_s[16][132];
    __shared__ float b_s[16][132];
    int tid = threadIdx.x;
    int m0 = blockIdx.y * 128;
    int n0 = blockIdx.x * 128;
    int am = (tid >> 4) << 2;     // 0..60
    int an = (tid & 15) << 2;     // 0..60
    int lr = tid >> 2;            // 0..63
    int lk = (tid & 3) << 2;      // 0,4,8,12

    float acc[8][8];
#pragma unroll
    for (int i = 0; i < 8; i++)
#pragma unroll
        for (int j = 0; j < 8; j++) acc[i][j] = 0.f;

    for (int k0 = 0; k0 < HH; k0 += 16) {
        float4 v;
        v = *(const float4*)&g_seq[(size_t)(m0 + lr) * HH + k0 + lk];
        a_s[lk + 0][lr] = v.x; a_s[lk + 1][lr] = v.y; a_s[lk + 2][lr] = v.z; a_s[lk + 3][lr] = v.w;
        v = *(const float4*)&g_seq[(size_t)(m0 + lr + 64) * HH + k0 + lk];
        a_s[lk + 0][lr + 64] = v.x; a_s[lk + 1][lr + 64] = v.y; a_s[lk + 2][lr + 64] = v.z; a_s[lk + 3][lr + 64] = v.w;

        int gc = n0 + lr;
        int wr = ((gc & 3) << 8) | (gc >> 2);
        v = *(const float4*)&wih[(size_t)wr * HH + k0 + lk];
        b_s[lk + 0][lr] = v.x; b_s[lk + 1][lr] = v.y; b_s[lk + 2][lr] = v.z; b_s[lk + 3][lr] = v.w;
        gc = n0 + lr + 64;
        wr = ((gc & 3) << 8) | (gc >> 2);
        v = *(const float4*)&wih[(size_t)wr * HH + k0 + lk];
        b_s[lk + 0][lr + 64] = v.x; b_s[lk + 1][lr + 64] = v.y; b_s[lk + 2][lr + 64] = v.z; b_s[lk + 3][lr + 64] = v.w;
        __syncthreads();

#pragma unroll
        for (int k = 0; k < 16; k++) {
            float4 A0 = *(const float4*)&a_s[k][am];
            float4 A1 = *(const float4*)&a_s[k][am + 64];
            float4 B0 = *(const float4*)&b_s[k][an];
            float4 B1 = *(const float4*)&b_s[k][an + 64];
            float ar[8] = {A0.x, A0.y, A0.z, A0.w, A1.x, A1.y, A1.z, A1.w};
            float br[8] = {B0.x, B0.y, B0.z, B0.w, B1.x, B1.y, B1.z, B1.w};
#pragma unroll
            for (int i = 0; i < 8; i++)
#pragma unroll
                for (int j = 0; j < 8; j++)
                    acc[i][j] = fmaf(ar[i], br[j], acc[i][j]);
        }
        __syncthreads();
    }

    float bv[8];
#pragma unroll
    for (int jh = 0; jh < 2; jh++)
#pragma unroll
        for (int j = 0; j < 4; j++) {
            int gc = n0 + an + jh * 64 + j;
            int wr = ((gc & 3) << 8) | (gc >> 2);
            bv[jh * 4 + j] = bih[wr] + bhh[wr];
        }
#pragma unroll
    for (int ih = 0; ih < 2; ih++)
#pragma unroll
        for (int i = 0; i < 4; i++) {
            size_t m = (size_t)(m0 + am + ih * 64 + i);
#pragma unroll
            for (int jh = 0; jh < 2; jh++) {
                int gcb = n0 + an + jh * 64;
                float4 o;
                o.x = acc[ih * 4 + i][jh * 4 + 0] + bv[jh * 4 + 0];
                o.y = acc[ih * 4 + i][jh * 4 + 1] + bv[jh * 4 + 1];
                o.z = acc[ih * 4 + i][jh * 4 + 2] + bv[jh * 4 + 2];
                o.w = acc[ih * 4 + i][jh * 4 + 3] + bv[jh * 4 + 3];
                *(float4*)&g_xg[m * G4 + gcb] = o;
            }
        }
}

// -------- one LSTM time step: gates = xg[:,t,:] + h @ w_hh^T, cell update --------
// grid (8 j-blocks, 16 b-blocks), 256 threads. CTA tile: 32 batch x 32 units (128 gate cols)
// thread: 4 batch rows x (1 unit x 4 gates)
template <bool WRITE_Y>
__global__ void lstm_step(const float* __restrict__ whh, int t) {
    __shared__ float h_s[32][36];    // [k][b]
    __shared__ float w_s[32][132];   // [k][c], c = jlocal*4+gate
    int tid = threadIdx.x;
    int jb0 = blockIdx.x << 5;
    int bb0 = blockIdx.y << 5;
    const float* hprev = g_hbuf[t & 1];
    float* hnext = g_hbuf[(t & 1) ^ 1];

    int a4 = (tid >> 5) << 2;        // batch sub-tile base 0..28
    int jx = tid & 31;               // local unit
    int jx4 = jx << 2;

    int hr = tid >> 3;               // 0..31
    int hk = (tid & 7) << 2;         // 0..28
    int wc = tid & 127;              // 0..127
    int wk = (tid >> 7) << 4;        // 0 or 16
    int wrow = ((wc & 3) << 8) | (jb0 + (wc >> 2));

    float acc[4][4];
#pragma unroll
    for (int r = 0; r < 4; r++)
#pragma unroll
        for (int g = 0; g < 4; g++) acc[r][g] = 0.f;

    for (int k0 = 0; k0 < HH; k0 += 32) {
        float4 v = *(const float4*)&hprev[(size_t)(bb0 + hr) * HH + k0 + hk];
        h_s[hk + 0][hr] = v.x; h_s[hk + 1][hr] = v.y; h_s[hk + 2][hr] = v.z; h_s[hk + 3][hr] = v.w;
        const float* wp = whh + (size_t)wrow * HH + k0 + wk;
#pragma unroll
        for (int q = 0; q < 4; q++) {
            float4 w4 = *(const float4*)(wp + q * 4);
            w_s[wk + q * 4 + 0][wc] = w4.x; w_s[wk + q * 4 + 1][wc] = w4.y;
            w_s[wk + q * 4 + 2][wc] = w4.z; w_s[wk + q * 4 + 3][wc] = w4.w;
        }
        __syncthreads();
#pragma unroll
        for (int k = 0; k < 32; k++) {
            float4 hv = *(const float4*)&h_s[k][a4];
            float4 wv = *(const float4*)&w_s[k][jx4];
            float hrg[4] = {hv.x, hv.y, hv.z, hv.w};
            float wrg[4] = {wv.x, wv.y, wv.z, wv.w};
#pragma unroll
            for (int r = 0; r < 4; r++)
#pragma unroll
                for (int g = 0; g < 4; g++)
                    acc[r][g] = fmaf(hrg[r], wrg[g], acc[r][g]);
        }
        __syncthreads();
    }

    int j = jb0 + jx;
#pragma unroll
    for (int r = 0; r < 4; r++) {
        int b = bb0 + a4 + r;
        float4 xg = *(const float4*)&g_xg[((size_t)b * SS + t) * G4 + (size_t)j * 4];
        float iv = sigm(acc[r][0] + xg.x);
        float fv = sigm(acc[r][1] + xg.y);
        float gv = tanhf(acc[r][2] + xg.z);
        float ov = sigm(acc[r][3] + xg.w);
        size_t idx = (size_t)b * HH + j;
        float cn = fmaf(fv, g_cbuf[idx], iv * gv);
        float hn = ov * tanhf(cn);
        g_cbuf[idx] = cn;
        hnext[idx] = hn;
        if (WRITE_Y) g_seq[((size_t)b * SS + t) * HH + j] = hn;
    }
}

// -------- copy final h/c of a layer into d_out --------
__global__ void save_hc(float* __restrict__ oh, float* __restrict__ oc) {
    int i = blockIdx.x * blockDim.x + threadIdx.x;
    if (i < BB * HH) { oh[i] = g_hbuf[0][i]; oc[i] = g_cbuf[i]; }
}

// -------- head: layernorm(h1) -> relu(w1) -> w2 -> mask --------
__global__ void head_kernel(const float* __restrict__ mask,
                            const float* __restrict__ ln_g, const float* __restrict__ ln_b,
                            const float* __restrict__ w1, const float* __restrict__ b1,
                            const float* __restrict__ w2, const float* __restrict__ b2,
                            float* __restrict__ out_logits) {
    int b = blockIdx.x;
    int tid = threadIdx.x;
    __shared__ float sh[HH];
    __shared__ float r1[8], r2[8];
    __shared__ float stats[2];
    __shared__ float hdn[32];

    float v = g_hbuf[0][(size_t)b * HH + tid];
    float s1 = v, s2 = v * v;
#pragma unroll
    for (int off = 16; off > 0; off >>= 1) {
        s1 += __shfl_down_sync(0xffffffffu, s1, off);
        s2 += __shfl_down_sync(0xffffffffu, s2, off);
    }
    if ((tid & 31) == 0) { r1[tid >> 5] = s1; r2[tid >> 5] = s2; }
    __syncthreads();
    if (tid == 0) {
        float t1 = 0.f, t2 = 0.f;
        for (int i = 0; i < 8; i++) { t1 += r1[i]; t2 += r2[i]; }
        float mu = t1 * (1.f / HH);
        float var = t2 * (1.f / HH) - mu * mu;
        stats[0] = mu;
        stats[1] = rsqrtf(var + 1e-5f);
    }
    __syncthreads();
    sh[tid] = (v - stats[0]) * stats[1] * ln_g[tid] + ln_b[tid];
    __syncthreads();

    int u = tid >> 3, p = tid & 7;
    float part = 0.f;
#pragma unroll
    for (int k = p; k < HH; k += 8) part = fmaf(sh[k], w1[u * HH + k], part);
    part += __shfl_down_sync(0xffffffffu, part, 4);
    part += __shfl_down_sync(0xffffffffu, part, 2);
    part += __shfl_down_sync(0xffffffffu, part, 1);
    if (p == 0) hdn[u] = fmaxf(part + b1[u], 0.f);
    __syncthreads();

    if (tid < AA) {
        float acc = b2[tid];
#pragma unroll
        for (int k = 0; k < 32; k++) acc = fmaf(hdn[k], w2[tid * 32 + k], acc);
        acc += (1.f - mask[(size_t)b * AA + tid]) * -1e9f;
        out_logits[(size_t)b * AA + tid] = acc;
    }
}

extern "C" void kernel_launch(void* const* d_in, const int* in_sizes, int n_in,
                              void* d_out, int out_size) {
    (void)in_sizes; (void)n_in; (void)out_size;
    const float* x     = (const float*)d_in[0];
    const float* mask  = (const float*)d_in[1];
    const float* W_emb = (const float*)d_in[2];
    const float* b_emb = (const float*)d_in[3];
    const float* w_ih0 = (const float*)d_in[4];
    const float* w_hh0 = (const float*)d_in[5];
    const float* b_ih0 = (const float*)d_in[6];
    const float* b_hh0 = (const float*)d_in[7];
    const float* w_ih1 = (const float*)d_in[8];
    const float* w_hh1 = (const float*)d_in[9];
    const float* b_ih1 = (const float*)d_in[10];
    const float* b_hh1 = (const float*)d_in[11];
    const float* ln_g  = (const float*)d_in[12];
    const float* ln_b  = (const float*)d_in[13];
    const float* w1    = (const float*)d_in[14];
    const float* b1    = (const float*)d_in[15];
    const float* w2    = (const float*)d_in[16];
    const float* b2    = (const float*)d_in[17];

    float* out        = (float*)d_out;
    float* out_logits = out;                       // [512, 9]
    float* out_h0     = out + BB * AA;             // stack_h[0]
    float* out_h1     = out_h0 + BB * HH;          // stack_h[1]
    float* out_c0     = out_h1 + BB * HH;          // stack_c[0]
    float* out_c1     = out_c0 + BB * HH;          // stack_c[1]

    dim3 gemm_grid(G4 / 128, (BB * SS) / 128);     // (8, 1024)
    dim3 step_grid(HH / 32, BB / 32);              // (8, 16)

    // embedding
    emb_kernel<<<(BB * SS) / 8, 256>>>(x, W_emb, b_emb);

    // layer 0: precompute input gates, then recurrence
    xg_gemm<<<gemm_grid, 256>>>(w_ih0, b_ih0, b_hh0);
    zero_hc_kernel<<<(BB * HH) / 256, 256>>>();
    for (int t = 0; t < SS; t++)
        lstm_step<true><<<step_grid, 256>>>(w_hh0, t);
    save_hc<<<(BB * HH) / 256, 256>>>(out_h0, out_c0);

    // layer 1 (y0 now lives in g_seq)
    xg_gemm<<<gemm_grid, 256>>>(w_ih1, b_ih1, b_hh1);
    zero_hc_kernel<<<(BB * HH) / 256, 256>>>();
    for (int t = 0; t < SS; t++)
        lstm_step<false><<<step_grid, 256>>>(w_hh1, t);
    save_hc<<<(BB * HH) / 256, 256>>>(out_h1, out_c1);

    // head: last == final h1
    head_kernel<<<BB, 256>>>(mask, ln_g, ln_b, w1, b1, w2, b2, out_logits);
}

// round 7
// speedup vs baseline: 1.0016x; 1.0016x over previous
#include <cuda_runtime.h>
#include <math.h>

#define BB 512
#define SS 256
#define ID 12
#define HH 256
#define AA 9
#define G4 1024   // 4*HH

// -------- scratch (static device allocations; no runtime alloc) --------
static __device__ float g_seq[(size_t)BB * SS * HH];   // emb, then reused as y0
static __device__ float g_xg[(size_t)BB * SS * G4];    // precomputed input gates, cols gc = j*4+gate
static __device__ float g_hbuf[2][BB * HH];            // ping-pong hidden state
static __device__ float g_cbuf[BB * HH];               // cell state

__device__ __forceinline__ float sigm(float x) { return 1.f / (1.f + expf(-x)); }

// -------- zero h/c before each layer --------
__global__ void zero_hc_kernel() {
    int i = blockIdx.x * blockDim.x + threadIdx.x;
    if (i < BB * HH) { g_hbuf[0][i] = 0.f; g_cbuf[i] = 0.f; }
}

// -------- emb = relu(x @ W_emb^T + b_emb), x:[B*S,12], W:[256,12] --------
__global__ void emb_kernel(const float* __restrict__ x,
                           const float* __restrict__ W,
                           const float* __restrict__ bias) {
    __shared__ float ws[HH * ID];      // 12 KB
    __shared__ float xs[8][ID];
    int tid = threadIdx.x;
    for (int i = tid; i < HH * ID; i += 256) ws[i] = W[i];
    size_t row0 = (size_t)blockIdx.x * 8;
    if (tid < 8 * ID) xs[tid / ID][tid % ID] = x[row0 * ID + tid];
    __syncthreads();
    float b = bias[tid];
#pragma unroll
    for (int r = 0; r < 8; r++) {
        float acc = b;
#pragma unroll
        for (int i = 0; i < ID; i++) acc = fmaf(xs[r][i], ws[tid * ID + i], acc);
        g_seq[(row0 + r) * HH + tid] = fmaxf(acc, 0.f);
    }
}

// -------- xg[M,1024] = g_seq[M,256] @ w_ih^T  + (b_ih+b_hh), permuted cols --------
// output col gc -> weight row wr = (gc&3)*256 + (gc>>2)
// 128x128 tile, BK=16, 256 threads, 8x8 micro-tile (split 4+4)
__global__ void xg_gemm(const float* __restrict__ wih,
                        const float* __restrict__ bih,
                        const float* __restrict__ bhh) {
    __shared__ float a_s[16][132];
    __shared__ float b_s[16][132];
    int tid = threadIdx.x;
    int m0 = blockIdx.y * 128;
    int n0 = blockIdx.x * 128;
    int am = (tid >> 4) << 2;     // 0..60
    int an = (tid & 15) << 2;     // 0..60
    int lr = tid >> 2;            // 0..63
    int lk = (tid & 3) << 2;      // 0,4,8,12

    float acc[8][8];
#pragma unroll
    for (int i = 0; i < 8; i++)
#pragma unroll
        for (int j = 0; j < 8; j++) acc[i][j] = 0.f;

    for (int k0 = 0; k0 < HH; k0 += 16) {
        float4 v;
        v = *(const float4*)&g_seq[(size_t)(m0 + lr) * HH + k0 + lk];
        a_s[lk + 0][lr] = v.x; a_s[lk + 1][lr] = v.y; a_s[lk + 2][lr] = v.z; a_s[lk + 3][lr] = v.w;
        v = *(const float4*)&g_seq[(size_t)(m0 + lr + 64) * HH + k0 + lk];
        a_s[lk + 0][lr + 64] = v.x; a_s[lk + 1][lr + 64] = v.y; a_s[lk + 2][lr + 64] = v.z; a_s[lk + 3][lr + 64] = v.w;

        int gc = n0 + lr;
        int wr = ((gc & 3) << 8) | (gc >> 2);
        v = *(const float4*)&wih[(size_t)wr * HH + k0 + lk];
        b_s[lk + 0][lr] = v.x; b_s[lk + 1][lr] = v.y; b_s[lk + 2][lr] = v.z; b_s[lk + 3][lr] = v.w;
        gc = n0 + lr + 64;
        wr = ((gc & 3) << 8) | (gc >> 2);
        v = *(const float4*)&wih[(size_t)wr * HH + k0 + lk];
        b_s[lk + 0][lr + 64] = v.x; b_s[lk + 1][lr + 64] = v.y; b_s[lk + 2][lr + 64] = v.z; b_s[lk + 3][lr + 64] = v.w;
        __syncthreads();

#pragma unroll
        for (int k = 0; k < 16; k++) {
            float4 A0 = *(const float4*)&a_s[k][am];
            float4 A1 = *(const float4*)&a_s[k][am + 64];
            float4 B0 = *(const float4*)&b_s[k][an];
            float4 B1 = *(const float4*)&b_s[k][an + 64];
            float ar[8] = {A0.x, A0.y, A0.z, A0.w, A1.x, A1.y, A1.z, A1.w};
            float br[8] = {B0.x, B0.y, B0.z, B0.w, B1.x, B1.y, B1.z, B1.w};
#pragma unroll
            for (int i = 0; i < 8; i++)
#pragma unroll
                for (int j = 0; j < 8; j++)
                    acc[i][j] = fmaf(ar[i], br[j], acc[i][j]);
        }
        __syncthreads();
    }

    float bv[8];
#pragma unroll
    for (int jh = 0; jh < 2; jh++)
#pragma unroll
        for (int j = 0; j < 4; j++) {
            int gc = n0 + an + jh * 64 + j;
            int wr = ((gc & 3) << 8) | (gc >> 2);
            bv[jh * 4 + j] = bih[wr] + bhh[wr];
        }
#pragma unroll
    for (int ih = 0; ih < 2; ih++)
#pragma unroll
        for (int i = 0; i < 4; i++) {
            size_t m = (size_t)(m0 + am + ih * 64 + i);
#pragma unroll
            for (int jh = 0; jh < 2; jh++) {
                int gcb = n0 + an + jh * 64;
                float4 o;
                o.x = acc[ih * 4 + i][jh * 4 + 0] + bv[jh * 4 + 0];
                o.y = acc[ih * 4 + i][jh * 4 + 1] + bv[jh * 4 + 1];
                o.z = acc[ih * 4 + i][jh * 4 + 2] + bv[jh * 4 + 2];
                o.w = acc[ih * 4 + i][jh * 4 + 3] + bv[jh * 4 + 3];
                *(float4*)&g_xg[m * G4 + gcb] = o;
            }
        }
}

// -------- one LSTM time step: gates = xg[:,t,:] + h @ w_hh^T, cell update --------
// grid (8 j-blocks, 16 b-blocks), 256 threads. CTA tile: 32 batch x 32 units (128 gate cols)
// thread: 4 batch rows x (1 unit x 4 gates)
template <bool WRITE_Y>
__global__ void lstm_step(const float* __restrict__ whh, int t) {
    __shared__ float h_s[32][36];    // [k][b]
    __shared__ float w_s[32][132];   // [k][c], c = jlocal*4+gate
    int tid = threadIdx.x;
    int jb0 = blockIdx.x << 5;
    int bb0 = blockIdx.y << 5;
    const float* hprev = g_hbuf[t & 1];
    float* hnext = g_hbuf[(t & 1) ^ 1];

    int a4 = (tid >> 5) << 2;        // batch sub-tile base 0..28
    int jx = tid & 31;               // local unit
    int jx4 = jx << 2;

    int hr = tid >> 3;               // 0..31
    int hk = (tid & 7) << 2;         // 0..28
    int wc = tid & 127;              // 0..127
    int wk = (tid >> 7) << 4;        // 0 or 16
    int wrow = ((wc & 3) << 8) | (jb0 + (wc >> 2));

    float acc[4][4];
#pragma unroll
    for (int r = 0; r < 4; r++)
#pragma unroll
        for (int g = 0; g < 4; g++) acc[r][g] = 0.f;

    for (int k0 = 0; k0 < HH; k0 += 32) {
        float4 v = *(const float4*)&hprev[(size_t)(bb0 + hr) * HH + k0 + hk];
        h_s[hk + 0][hr] = v.x; h_s[hk + 1][hr] = v.y; h_s[hk + 2][hr] = v.z; h_s[hk + 3][hr] = v.w;
        const float* wp = whh + (size_t)wrow * HH + k0 + wk;
#pragma unroll
        for (int q = 0; q < 4; q++) {
            float4 w4 = *(const float4*)(wp + q * 4);
            w_s[wk + q * 4 + 0][wc] = w4.x; w_s[wk + q * 4 + 1][wc] = w4.y;
            w_s[wk + q * 4 + 2][wc] = w4.z; w_s[wk + q * 4 + 3][wc] = w4.w;
        }
        __syncthreads();
#pragma unroll
        for (int k = 0; k < 32; k++) {
            float4 hv = *(const float4*)&h_s[k][a4];
            float4 wv = *(const float4*)&w_s[k][jx4];
            float hrg[4] = {hv.x, hv.y, hv.z, hv.w};
            float wrg[4] = {wv.x, wv.y, wv.z, wv.w};
#pragma unroll
            for (int r = 0; r < 4; r++)
#pragma unroll
                for (int g = 0; g < 4; g++)
                    acc[r][g] = fmaf(hrg[r], wrg[g], acc[r][g]);
        }
        __syncthreads();
    }

    int j = jb0 + jx;
#pragma unroll
    for (int r = 0; r < 4; r++) {
        int b = bb0 + a4 + r;
        float4 xg = *(const float4*)&g_xg[((size_t)b * SS + t) * G4 + (size_t)j * 4];
        float iv = sigm(acc[r][0] + xg.x);
        float fv = sigm(acc[r][1] + xg.y);
        float gv = tanhf(acc[r][2] + xg.z);
        float ov = sigm(acc[r][3] + xg.w);
        size_t idx = (size_t)b * HH + j;
        float cn = fmaf(fv, g_cbuf[idx], iv * gv);
        float hn = ov * tanhf(cn);
        g_cbuf[idx] = cn;
        hnext[idx] = hn;
        if (WRITE_Y) g_seq[((size_t)b * SS + t) * HH + j] = hn;
    }
}

// -------- copy final h/c of a layer into d_out --------
__global__ void save_hc(float* __restrict__ oh, float* __restrict__ oc) {
    int i = blockIdx.x * blockDim.x + threadIdx.x;
    if (i < BB * HH) { oh[i] = g_hbuf[0][i]; oc[i] = g_cbuf[i]; }
}

// -------- head: layernorm(h1) -> relu(w1) -> w2 -> mask --------
__global__ void head_kernel(const float* __restrict__ mask,
                            const float* __restrict__ ln_g, const float* __restrict__ ln_b,
                            const float* __restrict__ w1, const float* __restrict__ b1,
                            const float* __restrict__ w2, const float* __restrict__ b2,
                            float* __restrict__ out_logits) {
    int b = blockIdx.x;
    int tid = threadIdx.x;
    __shared__ float sh[HH];
    __shared__ float r1[8], r2[8];
    __shared__ float stats[2];
    __shared__ float hdn[32];

    float v = g_hbuf[0][(size_t)b * HH + tid];
    float s1 = v, s2 = v * v;
#pragma unroll
    for (int off = 16; off > 0; off >>= 1) {
        s1 += __shfl_down_sync(0xffffffffu, s1, off);
        s2 += __shfl_down_sync(0xffffffffu, s2, off);
    }
    if ((tid & 31) == 0) { r1[tid >> 5] = s1; r2[tid >> 5] = s2; }
    __syncthreads();
    if (tid == 0) {
        float t1 = 0.f, t2 = 0.f;
        for (int i = 0; i < 8; i++) { t1 += r1[i]; t2 += r2[i]; }
        float mu = t1 * (1.f / HH);
        float var = t2 * (1.f / HH) - mu * mu;
        stats[0] = mu;
        stats[1] = rsqrtf(var + 1e-5f);
    }
    __syncthreads();
    sh[tid] = (v - stats[0]) * stats[1] * ln_g[tid] + ln_b[tid];
    __syncthreads();

    int u = tid >> 3, p = tid & 7;
    float part = 0.f;
#pragma unroll
    for (int k = p; k < HH; k += 8) part = fmaf(sh[k], w1[u * HH + k], part);
    part += __shfl_down_sync(0xffffffffu, part, 4);
    part += __shfl_down_sync(0xffffffffu, part, 2);
    part += __shfl_down_sync(0xffffffffu, part, 1);
    if (p == 0) hdn[u] = fmaxf(part + b1[u], 0.f);
    __syncthreads();

    if (tid < AA) {
        float acc = b2[tid];
#pragma unroll
        for (int k = 0; k < 32; k++) acc = fmaf(hdn[k], w2[tid * 32 + k], acc);
        acc += (1.f - mask[(size_t)b * AA + tid]) * -1e9f;
        out_logits[(size_t)b * AA + tid] = acc;
    }
}

extern "C" void kernel_launch(void* const* d_in, const int* in_sizes, int n_in,
                              void* d_out, int out_size) {
    (void)in_sizes; (void)n_in; (void)out_size;
    const float* x     = (const float*)d_in[0];
    const float* mask  = (const float*)d_in[1];
    const float* W_emb = (const float*)d_in[2];
    const float* b_emb = (const float*)d_in[3];
    const float* w_ih0 = (const float*)d_in[4];
    const float* w_hh0 = (const float*)d_in[5];
    const float* b_ih0 = (const float*)d_in[6];
    const float* b_hh0 = (const float*)d_in[7];
    const float* w_ih1 = (const float*)d_in[8];
    const float* w_hh1 = (const float*)d_in[9];
    const float* b_ih1 = (const float*)d_in[10];
    const float* b_hh1 = (const float*)d_in[11];
    const float* ln_g  = (const float*)d_in[12];
    const float* ln_b  = (const float*)d_in[13];
    const float* w1    = (const float*)d_in[14];
    const float* b1    = (const float*)d_in[15];
    const float* w2    = (const float*)d_in[16];
    const float* b2    = (const float*)d_in[17];

    float* out        = (float*)d_out;
    float* out_logits = out;                       // [512, 9]
    float* out_h0     = out + BB * AA;             // stack_h[0]
    float* out_h1     = out_h0 + BB * HH;          // stack_h[1]
    float* out_c0     = out_h1 + BB * HH;          // stack_c[0]
    float* out_c1     = out_c0 + BB * HH;          // stack_c[1]

    dim3 gemm_grid(G4 / 128, (BB * SS) / 128);     // (8, 1024)
    dim3 step_grid(HH / 32, BB / 32);              // (8, 16)

    // embedding
    emb_kernel<<<(BB * SS) / 8, 256>>>(x, W_emb, b_emb);

    // layer 0: precompute input gates, then recurrence
    xg_gemm<<<gemm_grid, 256>>>(w_ih0, b_ih0, b_hh0);
    zero_hc_kernel<<<(BB * HH) / 256, 256>>>();
    for (int t = 0; t < SS; t++)
        lstm_step<true><<<step_grid, 256>>>(w_hh0, t);
    save_hc<<<(BB * HH) / 256, 256>>>(out_h0, out_c0);

    // layer 1 (y0 now lives in g_seq)
    xg_gemm<<<gemm_grid, 256>>>(w_ih1, b_ih1, b_hh1);
    zero_hc_kernel<<<(BB * HH) / 256, 256>>>();
    for (int t = 0; t < SS; t++)
        lstm_step<false><<<step_grid, 256>>>(w_hh1, t);
    save_hc<<<(BB * HH) / 256, 256>>>(out_h1, out_c1);

    // head: last == final h1
    head_kernel<<<BB, 256>>>(mask, ln_g, ln_b, w1, b1, w2, b2, out_logits);
}

// round 8
// speedup vs baseline: 1.2912x; 1.2892x over previous
#include <cuda_runtime.h>
#include <math.h>

#define BB 512
#define SS 256
#define ID 12
#define HH 256
#define AA 9
#define G4 1024   // 4*HH
#define NCTA 128

// -------- scratch (static device allocations; no runtime alloc) --------
static __device__ float g_seq[(size_t)BB * SS * HH];   // emb, then reused as y0
static __device__ float g_xg[(size_t)BB * SS * G4];    // precomputed input gates, cols gc = j*4+gate
static __device__ float g_hbuf[2][BB * HH];            // ping-pong hidden state
static __device__ unsigned g_count;                    // grid barrier arrivals
static __device__ volatile unsigned g_gen;             // grid barrier generation

__device__ __forceinline__ float sigm(float x) { return 1.f / (1.f + expf(-x)); }

// software grid barrier: all NCTA CTAs are guaranteed co-resident (1 CTA/SM by smem)
__device__ __forceinline__ void grid_sync() {
    __threadfence();          // publish this thread's global writes
    __syncthreads();
    if (threadIdx.x == 0) {
        unsigned old = g_gen;
        unsigned t = atomicAdd(&g_count, 1);
        if (t == NCTA - 1) {
            g_count = 0;
            __threadfence();
            g_gen = old + 1;
        } else {
            while (g_gen == old) __nanosleep(20);
            __threadfence();
        }
    }
    __syncthreads();
}

// -------- emb = relu(x @ W_emb^T + b_emb), x:[B*S,12], W:[256,12] --------
__global__ void emb_kernel(const float* __restrict__ x,
                           const float* __restrict__ W,
                           const float* __restrict__ bias) {
    __shared__ float ws[HH * ID];      // 12 KB
    __shared__ float xs[8][ID];
    int tid = threadIdx.x;
    for (int i = tid; i < HH * ID; i += 256) ws[i] = W[i];
    size_t row0 = (size_t)blockIdx.x * 8;
    if (tid < 8 * ID) xs[tid / ID][tid % ID] = x[row0 * ID + tid];
    __syncthreads();
    float b = bias[tid];
#pragma unroll
    for (int r = 0; r < 8; r++) {
        float acc = b;
#pragma unroll
        for (int i = 0; i < ID; i++) acc = fmaf(xs[r][i], ws[tid * ID + i], acc);
        g_seq[(row0 + r) * HH + tid] = fmaxf(acc, 0.f);
    }
}

// -------- xg[M,1024] = g_seq[M,256] @ w_ih^T  + (b_ih+b_hh), permuted cols --------
// output col gc -> weight row wr = (gc&3)*256 + (gc>>2)
__global__ void xg_gemm(const float* __restrict__ wih,
                        const float* __restrict__ bih,
                        const float* __restrict__ bhh) {
    __shared__ float a_s[16][132];
    __shared__ float b_s[16][132];
    int tid = threadIdx.x;
    int m0 = blockIdx.y * 128;
    int n0 = blockIdx.x * 128;
    int am = (tid >> 4) << 2;
    int an = (tid & 15) << 2;
    int lr = tid >> 2;
    int lk = (tid & 3) << 2;

    float acc[8][8];
#pragma unroll
    for (int i = 0; i < 8; i++)
#pragma unroll
        for (int j = 0; j < 8; j++) acc[i][j] = 0.f;

    for (int k0 = 0; k0 < HH; k0 += 16) {
        float4 v;
        v = *(const float4*)&g_seq[(size_t)(m0 + lr) * HH + k0 + lk];
        a_s[lk + 0][lr] = v.x; a_s[lk + 1][lr] = v.y; a_s[lk + 2][lr] = v.z; a_s[lk + 3][lr] = v.w;
        v = *(const float4*)&g_seq[(size_t)(m0 + lr + 64) * HH + k0 + lk];
        a_s[lk + 0][lr + 64] = v.x; a_s[lk + 1][lr + 64] = v.y; a_s[lk + 2][lr + 64] = v.z; a_s[lk + 3][lr + 64] = v.w;

        int gc = n0 + lr;
        int wr = ((gc & 3) << 8) | (gc >> 2);
        v = *(const float4*)&wih[(size_t)wr * HH + k0 + lk];
        b_s[lk + 0][lr] = v.x; b_s[lk + 1][lr] = v.y; b_s[lk + 2][lr] = v.z; b_s[lk + 3][lr] = v.w;
        gc = n0 + lr + 64;
        wr = ((gc & 3) << 8) | (gc >> 2);
        v = *(const float4*)&wih[(size_t)wr * HH + k0 + lk];
        b_s[lk + 0][lr + 64] = v.x; b_s[lk + 1][lr + 64] = v.y; b_s[lk + 2][lr + 64] = v.z; b_s[lk + 3][lr + 64] = v.w;
        __syncthreads();

#pragma unroll
        for (int k = 0; k < 16; k++) {
            float4 A0 = *(const float4*)&a_s[k][am];
            float4 A1 = *(const float4*)&a_s[k][am + 64];
            float4 B0 = *(const float4*)&b_s[k][an];
            float4 B1 = *(const float4*)&b_s[k][an + 64];
            float ar[8] = {A0.x, A0.y, A0.z, A0.w, A1.x, A1.y, A1.z, A1.w};
            float br[8] = {B0.x, B0.y, B0.z, B0.w, B1.x, B1.y, B1.z, B1.w};
#pragma unroll
            for (int i = 0; i < 8; i++)
#pragma unroll
                for (int j = 0; j < 8; j++)
                    acc[i][j] = fmaf(ar[i], br[j], acc[i][j]);
        }
        __syncthreads();
    }

    float bv[8];
#pragma unroll
    for (int jh = 0; jh < 2; jh++)
#pragma unroll
        for (int j = 0; j < 4; j++) {
            int gc = n0 + an + jh * 64 + j;
            int wr = ((gc & 3) << 8) | (gc >> 2);
            bv[jh * 4 + j] = bih[wr] + bhh[wr];
        }
#pragma unroll
    for (int ih = 0; ih < 2; ih++)
#pragma unroll
        for (int i = 0; i < 4; i++) {
            size_t m = (size_t)(m0 + am + ih * 64 + i);
#pragma unroll
            for (int jh = 0; jh < 2; jh++) {
                int gcb = n0 + an + jh * 64;
                float4 o;
                o.x = acc[ih * 4 + i][jh * 4 + 0] + bv[jh * 4 + 0];
                o.y = acc[ih * 4 + i][jh * 4 + 1] + bv[jh * 4 + 1];
                o.z = acc[ih * 4 + i][jh * 4 + 2] + bv[jh * 4 + 2];
                o.w = acc[ih * 4 + i][jh * 4 + 3] + bv[jh * 4 + 3];
                *(float4*)&g_xg[m * G4 + gcb] = o;
            }
        }
}

// -------- persistent LSTM layer: 256 steps in one launch --------
// 128 CTAs = 8 j-groups (32 units = 128 gate cols) x 16 batch-groups (32 batches).
// Weights (128 cols x 256 K = 128KB) staged in smem ONCE. c in registers for whole layer.
// thread = 4 batches x 1 unit (4 gates); grid barrier between steps.
template <bool WRITE_Y>
__global__ void __launch_bounds__(256, 1) lstm_layer(const float* __restrict__ whh,
                                                     float* __restrict__ out_h,
                                                     float* __restrict__ out_c) {
    extern __shared__ float sm[];
    float* w_s = sm;                 // [256][128]  k-major, col c = jlocal*4+gate
    float* h_s = sm + 256 * 128;     // [256][36]   k-major, padded

    int tid = threadIdx.x;
    int jb0 = (blockIdx.x & 7) << 5;     // unit group base
    int bb0 = (blockIdx.x >> 3) << 5;    // batch group base

    // ---- stage weight tile once: conflict-free STS (lanes = consecutive cols) ----
    {
        int c = tid & 127;               // local gate col
        int kh = (tid >> 7) << 7;        // 0 or 128
        int gate = c & 3;
        int unit = jb0 + (c >> 2);
        const float* wrow = whh + (size_t)(gate * HH + unit) * HH + kh;
#pragma unroll
        for (int q = 0; q < 32; q++) {
            float4 v = *(const float4*)(wrow + q * 4);
            int k = kh + q * 4;
            w_s[(k + 0) * 128 + c] = v.x;
            w_s[(k + 1) * 128 + c] = v.y;
            w_s[(k + 2) * 128 + c] = v.z;
            w_s[(k + 3) * 128 + c] = v.w;
        }
    }
    __syncthreads();

    int a4 = (tid >> 5) << 2;            // batch sub-tile base (per warp)
    int jx = tid & 31;                   // local unit = lane
    int j = jb0 + jx;
    int sb = tid >> 3;                   // staging: batch lane 0..31
    int sk = (tid & 7) << 2;             // staging: k base

    float c_reg[4] = {0.f, 0.f, 0.f, 0.f};
    float hl[4] = {0.f, 0.f, 0.f, 0.f};

    for (int t = 0; t < SS; t++) {
        // prefetch this step's xg into registers (hides DRAM latency behind K-loop)
        float4 xgv[4];
#pragma unroll
        for (int r = 0; r < 4; r++)
            xgv[r] = *(const float4*)&g_xg[((size_t)(bb0 + a4 + r) * SS + t) * G4 + (size_t)j * 4];

        float acc[4][4];
#pragma unroll
        for (int r = 0; r < 4; r++)
#pragma unroll
            for (int g = 0; g < 4; g++) acc[r][g] = 0.f;

        if (t > 0) {
            // stage h_prev [32 b x 256 k] -> h_s[k][b]; __ldcg: L1 may hold stale lines
            const float* hp = g_hbuf[t & 1] + (size_t)(bb0 + sb) * HH;
#pragma unroll
            for (int q = 0; q < 8; q++) {
                int k = sk + q * 32;
                float4 v = __ldcg((const float4*)(hp + k));
                h_s[(k + 0) * 36 + sb] = v.x;
                h_s[(k + 1) * 36 + sb] = v.y;
                h_s[(k + 2) * 36 + sb] = v.z;
                h_s[(k + 3) * 36 + sb] = v.w;
            }
            __syncthreads();

#pragma unroll 4
            for (int k = 0; k < HH; k++) {
                float4 hv = *(const float4*)&h_s[k * 36 + a4];       // broadcast within warp
                float4 wv = *(const float4*)&w_s[k * 128 + (jx << 2)];
                float hr[4] = {hv.x, hv.y, hv.z, hv.w};
                float wr[4] = {wv.x, wv.y, wv.z, wv.w};
#pragma unroll
                for (int r = 0; r < 4; r++)
#pragma unroll
                    for (int g = 0; g < 4; g++)
                        acc[r][g] = fmaf(hr[r], wr[g], acc[r][g]);
            }
        }

        float* hnext = g_hbuf[(t & 1) ^ 1];
#pragma unroll
        for (int r = 0; r < 4; r++) {
            float iv = sigm(acc[r][0] + xgv[r].x);
            float fv = sigm(acc[r][1] + xgv[r].y);
            float gv = tanhf(acc[r][2] + xgv[r].z);
            float ov = sigm(acc[r][3] + xgv[r].w);
            c_reg[r] = fmaf(fv, c_reg[r], iv * gv);
            float hn = ov * tanhf(c_reg[r]);
            hl[r] = hn;
            int b = bb0 + a4 + r;
            hnext[(size_t)b * HH + j] = hn;
            if (WRITE_Y) g_seq[((size_t)b * SS + t) * HH + j] = hn;
        }

        grid_sync();
    }

    // epilogue: final h and c straight from registers
#pragma unroll
    for (int r = 0; r < 4; r++) {
        size_t idx = (size_t)(bb0 + a4 + r) * HH + j;
        out_h[idx] = hl[r];
        out_c[idx] = c_reg[r];
    }
}

// -------- head: layernorm(h1) -> relu(w1) -> w2 -> mask --------
__global__ void head_kernel(const float* __restrict__ mask,
                            const float* __restrict__ ln_g, const float* __restrict__ ln_b,
                            const float* __restrict__ w1, const float* __restrict__ b1,
                            const float* __restrict__ w2, const float* __restrict__ b2,
                            float* __restrict__ out_logits) {
    int b = blockIdx.x;
    int tid = threadIdx.x;
    __shared__ float sh[HH];
    __shared__ float r1[8], r2[8];
    __shared__ float stats[2];
    __shared__ float hdn[32];

    float v = g_hbuf[0][(size_t)b * HH + tid];
    float s1 = v, s2 = v * v;
#pragma unroll
    for (int off = 16; off > 0; off >>= 1) {
        s1 += __shfl_down_sync(0xffffffffu, s1, off);
        s2 += __shfl_down_sync(0xffffffffu, s2, off);
    }
    if ((tid & 31) == 0) { r1[tid >> 5] = s1; r2[tid >> 5] = s2; }
    __syncthreads();
    if (tid == 0) {
        float t1 = 0.f, t2 = 0.f;
        for (int i = 0; i < 8; i++) { t1 += r1[i]; t2 += r2[i]; }
        float mu = t1 * (1.f / HH);
        float var = t2 * (1.f / HH) - mu * mu;
        stats[0] = mu;
        stats[1] = rsqrtf(var + 1e-5f);
    }
    __syncthreads();
    sh[tid] = (v - stats[0]) * stats[1] * ln_g[tid] + ln_b[tid];
    __syncthreads();

    int u = tid >> 3, p = tid & 7;
    float part = 0.f;
#pragma unroll
    for (int k = p; k < HH; k += 8) part = fmaf(sh[k], w1[u * HH + k], part);
    part += __shfl_down_sync(0xffffffffu, part, 4);
    part += __shfl_down_sync(0xffffffffu, part, 2);
    part += __shfl_down_sync(0xffffffffu, part, 1);
    if (p == 0) hdn[u] = fmaxf(part + b1[u], 0.f);
    __syncthreads();

    if (tid < AA) {
        float acc = b2[tid];
#pragma unroll
        for (int k = 0; k < 32; k++) acc = fmaf(hdn[k], w2[tid * 32 + k], acc);
        acc += (1.f - mask[(size_t)b * AA + tid]) * -1e9f;
        out_logits[(size_t)b * AA + tid] = acc;
    }
}

extern "C" void kernel_launch(void* const* d_in, const int* in_sizes, int n_in,
                              void* d_out, int out_size) {
    (void)in_sizes; (void)n_in; (void)out_size;
    const float* x     = (const float*)d_in[0];
    const float* mask  = (const float*)d_in[1];
    const float* W_emb = (const float*)d_in[2];
    const float* b_emb = (const float*)d_in[3];
    const float* w_ih0 = (const float*)d_in[4];
    const float* w_hh0 = (const float*)d_in[5];
    const float* b_ih0 = (const float*)d_in[6];
    const float* b_hh0 = (const float*)d_in[7];
    const float* w_ih1 = (const float*)d_in[8];
    const float* w_hh1 = (const float*)d_in[9];
    const float* b_ih1 = (const float*)d_in[10];
    const float* b_hh1 = (const float*)d_in[11];
    const float* ln_g  = (const float*)d_in[12];
    const float* ln_b  = (const float*)d_in[13];
    const float* w1    = (const float*)d_in[14];
    const float* b1    = (const float*)d_in[15];
    const float* w2    = (const float*)d_in[16];
    const float* b2    = (const float*)d_in[17];

    float* out        = (float*)d_out;
    float* out_logits = out;                       // [512, 9]
    float* out_h0     = out + BB * AA;             // stack_h[0]
    float* out_h1     = out_h0 + BB * HH;          // stack_h[1]
    float* out_c0     = out_h1 + BB * HH;          // stack_c[0]
    float* out_c1     = out_c0 + BB * HH;          // stack_c[1]

    const int SMEM_BYTES = (256 * 128 + 256 * 36) * 4;   // 167,936 B (< 227KB cap)
    cudaFuncSetAttribute(lstm_layer<true>,
                         cudaFuncAttributeMaxDynamicSharedMemorySize, SMEM_BYTES);
    cudaFuncSetAttribute(lstm_layer<false>,
                         cudaFuncAttributeMaxDynamicSharedMemorySize, SMEM_BYTES);

    dim3 gemm_grid(G4 / 128, (BB * SS) / 128);     // (8, 1024)

    // embedding
    emb_kernel<<<(BB * SS) / 8, 256>>>(x, W_emb, b_emb);

    // layer 0: input-gate GEMM, then persistent recurrence (writes y0 to g_seq)
    xg_gemm<<<gemm_grid, 256>>>(w_ih0, b_ih0, b_hh0);
    lstm_layer<true><<<NCTA, 256, SMEM_BYTES>>>(w_hh0, out_h0, out_c0);

    // layer 1 (y0 now lives in g_seq)
    xg_gemm<<<gemm_grid, 256>>>(w_ih1, b_ih1, b_hh1);
    lstm_layer<false><<<NCTA, 256, SMEM_BYTES>>>(w_hh1, out_h1, out_c1);

    // head: last == final h1 (in g_hbuf[0])
    head_kernel<<<BB, 256>>>(mask, ln_g, ln_b, w1, b1, w2, b2, out_logits);
}

// round 10
// speedup vs baseline: 1.4429x; 1.1175x over previous
#include <cuda_runtime.h>
#include <cuda_bf16.h>
#include <math.h>
#include <stdint.h>

#define BB 512
#define SS 256
#define ID 12
#define HH 256
#define AA 9
#define G4 1024   // 4*HH
#define NCTA 128

// -------- scratch (static device allocations; no runtime alloc) --------
static __device__ float g_seq[(size_t)BB * SS * HH];   // emb, then reused as y0
static __device__ float g_xg[(size_t)BB * SS * G4];    // input gates, cols gc = j*4+gate
static __device__ float g_hbuf[2][BB * HH];            // ping-pong hidden state
static __device__ unsigned g_count;
static __device__ volatile unsigned g_gen;

__device__ __forceinline__ float sigm(float x) { return 1.f / (1.f + expf(-x)); }

__device__ __forceinline__ uint32_t smem_u32(const void* p) {
    uint32_t a;
    asm("{ .reg .u64 t; cvta.to.shared.u64 t, %1; cvt.u32.u64 %0, t; }" : "=r"(a) : "l"(p));
    return a;
}

// software grid barrier: all NCTA CTAs co-resident (1 CTA/SM by smem)
__device__ __forceinline__ void grid_sync() {
    __threadfence();
    __syncthreads();
    if (threadIdx.x == 0) {
        unsigned old = g_gen;
        unsigned t = atomicAdd(&g_count, 1);
        if (t == NCTA - 1) {
            g_count = 0;
            __threadfence();
            g_gen = old + 1;
        } else {
            while (g_gen == old) __nanosleep(20);
            __threadfence();
        }
    }
    __syncthreads();
}

// ---------------- warp-MMA helpers (compute_80-compatible, no arch-suffix gating) ----
__device__ __forceinline__ void ldm4(uint32_t* r, uint32_t addr) {
    asm volatile("ldmatrix.sync.aligned.m8n8.x4.shared.b16 {%0,%1,%2,%3}, [%4];"
                 : "=r"(r[0]), "=r"(r[1]), "=r"(r[2]), "=r"(r[3]) : "r"(addr));
}

__device__ __forceinline__ void mma_bf16(float* d, const uint32_t* a, uint32_t b0, uint32_t b1) {
    asm volatile(
        "mma.sync.aligned.m16n8k16.row.col.f32.bf16.bf16.f32 "
        "{%0,%1,%2,%3}, {%4,%5,%6,%7}, {%8,%9}, {%0,%1,%2,%3};"
        : "+f"(d[0]), "+f"(d[1]), "+f"(d[2]), "+f"(d[3])
        : "r"(a[0]), "r"(a[1]), "r"(a[2]), "r"(a[3]), "r"(b0), "r"(b1));
}

__device__ __forceinline__ uint32_t pk2(float a, float b) {
    return (uint32_t)__bfloat16_as_ushort(__float2bfloat16(a)) |
           ((uint32_t)__bfloat16_as_ushort(__float2bfloat16(b)) << 16);
}

// fp32x4 -> bf16 hi (8B) + bf16 lo residual (8B)
__device__ __forceinline__ void split_store(char* hp, char* lp, float4 v) {
    float hx = __bfloat162float(__float2bfloat16(v.x));
    float hy = __bfloat162float(__float2bfloat16(v.y));
    float hz = __bfloat162float(__float2bfloat16(v.z));
    float hw = __bfloat162float(__float2bfloat16(v.w));
    uint64_t hi = (uint64_t)pk2(v.x, v.y) | ((uint64_t)pk2(v.z, v.w) << 32);
    uint64_t lo = (uint64_t)pk2(v.x - hx, v.y - hy) | ((uint64_t)pk2(v.z - hz, v.w - hw) << 32);
    *(uint64_t*)hp = hi;
    *(uint64_t*)lp = lo;
}

// -------- emb = relu(x @ W_emb^T + b_emb) --------
__global__ void emb_kernel(const float* __restrict__ x,
                           const float* __restrict__ W,
                           const float* __restrict__ bias) {
    __shared__ float ws[HH * ID];
    __shared__ float xs[8][ID];
    int tid = threadIdx.x;
    for (int i = tid; i < HH * ID; i += 256) ws[i] = W[i];
    size_t row0 = (size_t)blockIdx.x * 8;
    if (tid < 8 * ID) xs[tid / ID][tid % ID] = x[row0 * ID + tid];
    __syncthreads();
    float b = bias[tid];
#pragma unroll
    for (int r = 0; r < 8; r++) {
        float acc = b;
#pragma unroll
        for (int i = 0; i < ID; i++) acc = fmaf(xs[r][i], ws[tid * ID + i], acc);
        g_seq[(row0 + r) * HH + tid] = fmaxf(acc, 0.f);
    }
}

// ===================== tensor-core xg GEMM (warp mma.sync, bf16 3-term split) =========
// xg[M,1024] = g_seq[M,256] @ wih^T (+b_ih+b_hh); output col gc -> weight row
// wr = (gc&3)*256 + (gc>>2). CTA tile 128x128, K=256 in 2 chunks of 128.
// smem bf16 tiles [128][136] (row stride 272B -> ldmatrix conflict-free).
#define RS 136                               // bf16 row stride
#define OFF_AHI 0
#define OFF_ALO (128 * RS * 2)               // 34816
#define OFF_BHI (2 * 128 * RS * 2)           // 69632
#define OFF_BLO (3 * 128 * RS * 2)           // 104448
#define OFF_BIAS (4 * 128 * RS * 2)          // 139264
#define XG_SMEM (OFF_BIAS + 512)             // 139776

__global__ void __launch_bounds__(256, 1) xg_mma(const float* __restrict__ wih,
                                                 const float* __restrict__ bih,
                                                 const float* __restrict__ bhh) {
    extern __shared__ char sp[];
    const uint32_t sb = smem_u32(sp);
    float* bias_s = (float*)(sp + OFF_BIAS);

    const int tid = threadIdx.x;
    const int lane = tid & 31;
    const int w = tid >> 5;
    const int wm0 = (w & 3) * 32;            // warp m base
    const int wn0 = (w >> 2) * 64;           // warp n base
    const int n0 = blockIdx.x * 128;
    const int m0 = blockIdx.y * 128;

    if (tid < 128) {
        int gc = n0 + tid;
        int wr = ((gc & 3) << 8) | (gc >> 2);
        bias_s[tid] = bih[wr] + bhh[wr];
    }

    float acc[2][8][4];
#pragma unroll
    for (int i = 0; i < 2; i++)
#pragma unroll
        for (int j = 0; j < 8; j++)
#pragma unroll
            for (int q = 0; q < 4; q++) acc[i][j][q] = 0.f;

    // ldmatrix per-lane address offsets (element units)
    const int a_row = (lane & 15);
    const int a_kof = (lane >> 4) << 3;
    const int b_row = (lane & 7) + ((lane >> 4) << 3);
    const int b_kof = ((lane >> 3) & 1) << 3;

#pragma unroll
    for (int ch = 0; ch < 2; ch++) {
        const int kc0 = ch << 7;
        // ---- load fp32, split bf16 hi/lo into smem ----
#pragma unroll
        for (int q = 0; q < 16; q++) {
            int p = tid + (q << 8);
            int r = p >> 5;
            int k = (p & 31) << 2;
            uint32_t so = (uint32_t)(r * RS + k) * 2;
            float4 va = *(const float4*)&g_seq[(size_t)(m0 + r) * HH + kc0 + k];
            split_store(sp + OFF_AHI + so, sp + OFF_ALO + so, va);
            int gc = n0 + r;
            int wr = ((gc & 3) << 8) | (gc >> 2);
            float4 vb = *(const float4*)&wih[(size_t)wr * HH + kc0 + k];
            split_store(sp + OFF_BHI + so, sp + OFF_BLO + so, vb);
        }
        __syncthreads();

#pragma unroll
        for (int ks = 0; ks < 8; ks++) {
            const int kb = ks << 4;
            uint32_t ah[2][4], al[2][4];
#pragma unroll
            for (int mt = 0; mt < 2; mt++) {
                uint32_t off = (uint32_t)((wm0 + mt * 16 + a_row) * RS + kb + a_kof) * 2;
                ldm4(ah[mt], sb + OFF_AHI + off);
                ldm4(al[mt], sb + OFF_ALO + off);
            }
#pragma unroll
            for (int np = 0; np < 4; np++) {
                uint32_t off = (uint32_t)((wn0 + np * 16 + b_row) * RS + kb + b_kof) * 2;
                uint32_t bh[4], bl[4];
                ldm4(bh, sb + OFF_BHI + off);
                ldm4(bl, sb + OFF_BLO + off);
#pragma unroll
                for (int mt = 0; mt < 2; mt++) {
                    mma_bf16(acc[mt][np * 2], ah[mt], bh[0], bh[1]);
                    mma_bf16(acc[mt][np * 2], ah[mt], bl[0], bl[1]);
                    mma_bf16(acc[mt][np * 2], al[mt], bh[0], bh[1]);
                    mma_bf16(acc[mt][np * 2 + 1], ah[mt], bh[2], bh[3]);
                    mma_bf16(acc[mt][np * 2 + 1], ah[mt], bl[2], bl[3]);
                    mma_bf16(acc[mt][np * 2 + 1], al[mt], bh[2], bh[3]);
                }
            }
        }
        __syncthreads();   // before next chunk overwrites tiles
    }

    // ---- epilogue: stage acc in smem (reuse Ahi+Alo region), coalesced out ----
    float* stg = (float*)sp;                 // [128][132] floats = 67,584 B <= 69,632
    const int g = lane >> 2, tg = lane & 3;
#pragma unroll
    for (int mt = 0; mt < 2; mt++)
#pragma unroll
        for (int nt = 0; nt < 8; nt++) {
            int row = wm0 + mt * 16 + g;
            int col = wn0 + nt * 8 + tg * 2;
            *(float2*)&stg[row * 132 + col] = make_float2(acc[mt][nt][0], acc[mt][nt][1]);
            *(float2*)&stg[(row + 8) * 132 + col] = make_float2(acc[mt][nt][2], acc[mt][nt][3]);
        }
    __syncthreads();

#pragma unroll
    for (int q = 0; q < 16; q++) {
        int p = tid + (q << 8);
        int r = p >> 5;
        int c = (p & 31) << 2;
        float4 o = *(const float4*)&stg[r * 132 + c];
        o.x += bias_s[c + 0];
        o.y += bias_s[c + 1];
        o.z += bias_s[c + 2];
        o.w += bias_s[c + 3];
        *(float4*)&g_xg[(size_t)(m0 + r) * G4 + n0 + c] = o;
    }
}

// -------- persistent LSTM layer (unchanged from R8) --------
template <bool WRITE_Y>
__global__ void __launch_bounds__(256, 1) lstm_layer(const float* __restrict__ whh,
                                                     float* __restrict__ out_h,
                                                     float* __restrict__ out_c) {
    extern __shared__ float sm[];
    float* w_s = sm;                 // [256][128]  k-major, col c = jlocal*4+gate
    float* h_s = sm + 256 * 128;     // [256][36]   k-major, padded

    int tid = threadIdx.x;
    int jb0 = (blockIdx.x & 7) << 5;
    int bb0 = (blockIdx.x >> 3) << 5;

    {
        int c = tid & 127;
        int kh = (tid >> 7) << 7;
        int gate = c & 3;
        int unit = jb0 + (c >> 2);
        const float* wrow = whh + (size_t)(gate * HH + unit) * HH + kh;
#pragma unroll
        for (int q = 0; q < 32; q++) {
            float4 v = *(const float4*)(wrow + q * 4);
            int k = kh + q * 4;
            w_s[(k + 0) * 128 + c] = v.x;
            w_s[(k + 1) * 128 + c] = v.y;
            w_s[(k + 2) * 128 + c] = v.z;
            w_s[(k + 3) * 128 + c] = v.w;
        }
    }
    __syncthreads();

    int a4 = (tid >> 5) << 2;
    int jx = tid & 31;
    int j = jb0 + jx;
    int sb = tid >> 3;
    int sk = (tid & 7) << 2;

    float c_reg[4] = {0.f, 0.f, 0.f, 0.f};
    float hl[4] = {0.f, 0.f, 0.f, 0.f};

    for (int t = 0; t < SS; t++) {
        float4 xgv[4];
#pragma unroll
        for (int r = 0; r < 4; r++)
            xgv[r] = *(const float4*)&g_xg[((size_t)(bb0 + a4 + r) * SS + t) * G4 + (size_t)j * 4];

        float acc[4][4];
#pragma unroll
        for (int r = 0; r < 4; r++)
#pragma unroll
            for (int g = 0; g < 4; g++) acc[r][g] = 0.f;

        if (t > 0) {
            const float* hp = g_hbuf[t & 1] + (size_t)(bb0 + sb) * HH;
#pragma unroll
            for (int q = 0; q < 8; q++) {
                int k = sk + q * 32;
                float4 v = __ldcg((const float4*)(hp + k));
                h_s[(k + 0) * 36 + sb] = v.x;
                h_s[(k + 1) * 36 + sb] = v.y;
                h_s[(k + 2) * 36 + sb] = v.z;
                h_s[(k + 3) * 36 + sb] = v.w;
            }
            __syncthreads();

#pragma unroll 4
            for (int k = 0; k < HH; k++) {
                float4 hv = *(const float4*)&h_s[k * 36 + a4];
                float4 wv = *(const float4*)&w_s[k * 128 + (jx << 2)];
                float hr[4] = {hv.x, hv.y, hv.z, hv.w};
                float wr[4] = {wv.x, wv.y, wv.z, wv.w};
#pragma unroll
                for (int r = 0; r < 4; r++)
#pragma unroll
                    for (int g = 0; g < 4; g++)
                        acc[r][g] = fmaf(hr[r], wr[g], acc[r][g]);
            }
        }

        float* hnext = g_hbuf[(t & 1) ^ 1];
#pragma unroll
        for (int r = 0; r < 4; r++) {
            float iv = sigm(acc[r][0] + xgv[r].x);
            float fv = sigm(acc[r][1] + xgv[r].y);
            float gv = tanhf(acc[r][2] + xgv[r].z);
            float ov = sigm(acc[r][3] + xgv[r].w);
            c_reg[r] = fmaf(fv, c_reg[r], iv * gv);
            float hn = ov * tanhf(c_reg[r]);
            hl[r] = hn;
            int b = bb0 + a4 + r;
            hnext[(size_t)b * HH + j] = hn;
            if (WRITE_Y) g_seq[((size_t)b * SS + t) * HH + j] = hn;
        }

        grid_sync();
    }

#pragma unroll
    for (int r = 0; r < 4; r++) {
        size_t idx = (size_t)(bb0 + a4 + r) * HH + j;
        out_h[idx] = hl[r];
        out_c[idx] = c_reg[r];
    }
}

// -------- head: layernorm(h1) -> relu(w1) -> w2 -> mask --------
__global__ void head_kernel(const float* __restrict__ mask,
                            const float* __restrict__ ln_g, const float* __restrict__ ln_b,
                            const float* __restrict__ w1, const float* __restrict__ b1,
                            const float* __restrict__ w2, const float* __restrict__ b2,
                            float* __restrict__ out_logits) {
    int b = blockIdx.x;
    int tid = threadIdx.x;
    __shared__ float sh[HH];
    __shared__ float r1[8], r2[8];
    __shared__ float stats[2];
    __shared__ float hdn[32];

    float v = g_hbuf[0][(size_t)b * HH + tid];
    float s1 = v, s2 = v * v;
#pragma unroll
    for (int off = 16; off > 0; off >>= 1) {
        s1 += __shfl_down_sync(0xffffffffu, s1, off);
        s2 += __shfl_down_sync(0xffffffffu, s2, off);
    }
    if ((tid & 31) == 0) { r1[tid >> 5] = s1; r2[tid >> 5] = s2; }
    __syncthreads();
    if (tid == 0) {
        float t1 = 0.f, t2 = 0.f;
        for (int i = 0; i < 8; i++) { t1 += r1[i]; t2 += r2[i]; }
        float mu = t1 * (1.f / HH);
        float var = t2 * (1.f / HH) - mu * mu;
        stats[0] = mu;
        stats[1] = rsqrtf(var + 1e-5f);
    }
    __syncthreads();
    sh[tid] = (v - stats[0]) * stats[1] * ln_g[tid] + ln_b[tid];
    __syncthreads();

    int u = tid >> 3, p = tid & 7;
    float part = 0.f;
#pragma unroll
    for (int k = p; k < HH; k += 8) part = fmaf(sh[k], w1[u * HH + k], part);
    part += __shfl_down_sync(0xffffffffu, part, 4);
    part += __shfl_down_sync(0xffffffffu, part, 2);
    part += __shfl_down_sync(0xffffffffu, part, 1);
    if (p == 0) hdn[u] = fmaxf(part + b1[u], 0.f);
    __syncthreads();

    if (tid < AA) {
        float acc = b2[tid];
#pragma unroll
        for (int k = 0; k < 32; k++) acc = fmaf(hdn[k], w2[tid * 32 + k], acc);
        acc += (1.f - mask[(size_t)b * AA + tid]) * -1e9f;
        out_logits[(size_t)b * AA + tid] = acc;
    }
}

extern "C" void kernel_launch(void* const* d_in, const int* in_sizes, int n_in,
                              void* d_out, int out_size) {
    (void)in_sizes; (void)n_in; (void)out_size;
    const float* x     = (const float*)d_in[0];
    const float* mask  = (const float*)d_in[1];
    const float* W_emb = (const float*)d_in[2];
    const float* b_emb = (const float*)d_in[3];
    const float* w_ih0 = (const float*)d_in[4];
    const float* w_hh0 = (const float*)d_in[5];
    const float* b_ih0 = (const float*)d_in[6];
    const float* b_hh0 = (const float*)d_in[7];
    const float* w_ih1 = (const float*)d_in[8];
    const float* w_hh1 = (const float*)d_in[9];
    const float* b_ih1 = (const float*)d_in[10];
    const float* b_hh1 = (const float*)d_in[11];
    const float* ln_g  = (const float*)d_in[12];
    const float* ln_b  = (const float*)d_in[13];
    const float* w1    = (const float*)d_in[14];
    const float* b1    = (const float*)d_in[15];
    const float* w2    = (const float*)d_in[16];
    const float* b2    = (const float*)d_in[17];

    float* out        = (float*)d_out;
    float* out_logits = out;
    float* out_h0     = out + BB * AA;
    float* out_h1     = out_h0 + BB * HH;
    float* out_c0     = out_h1 + BB * HH;
    float* out_c1     = out_c0 + BB * HH;

    const int LSTM_SMEM = (256 * 128 + 256 * 36) * 4;   // 167,936 B
    cudaFuncSetAttribute(lstm_layer<true>,
                         cudaFuncAttributeMaxDynamicSharedMemorySize, LSTM_SMEM);
    cudaFuncSetAttribute(lstm_layer<false>,
                         cudaFuncAttributeMaxDynamicSharedMemorySize, LSTM_SMEM);
    cudaFuncSetAttribute(xg_mma,
                         cudaFuncAttributeMaxDynamicSharedMemorySize, XG_SMEM);

    dim3 xg_grid(G4 / 128, (BB * SS) / 128);   // (8, 1024): n fastest -> A-tile L2 reuse

    emb_kernel<<<(BB * SS) / 8, 256>>>(x, W_emb, b_emb);

    // layer 0
    xg_mma<<<xg_grid, 256, XG_SMEM>>>(w_ih0, b_ih0, b_hh0);
    lstm_layer<true><<<NCTA, 256, LSTM_SMEM>>>(w_hh0, out_h0, out_c0);

    // layer 1 (y0 in g_seq)
    xg_mma<<<xg_grid, 256, XG_SMEM>>>(w_ih1, b_ih1, b_hh1);
    lstm_layer<false><<<NCTA, 256, LSTM_SMEM>>>(w_hh1, out_h1, out_c1);

    // head: last == final h1 (in g_hbuf[0])
    head_kernel<<<BB, 256>>>(mask, ln_g, ln_b, w1, b1, w2, b2, out_logits);
}

// round 12
// speedup vs baseline: 2.4767x; 1.7165x over previous
#include <cuda_runtime.h>
#include <cuda_bf16.h>
#include <math.h>
#include <stdint.h>

#define BB 512
#define SS 256
#define ID 12
#define HH 256
#define AA 9
#define G4 1024   // 4*HH
#define NCTA 128

// -------- scratch (static device allocations; no runtime alloc) --------
static __device__ float g_seq[(size_t)BB * SS * HH];   // emb, then reused as y0
static __device__ float g_xg[(size_t)BB * SS * G4];    // input gates, cols gc = j*4+gate
static __device__ float g_hbuf[2][BB * HH];            // ping-pong hidden state
static __device__ unsigned g_count;
static __device__ volatile unsigned g_gen;

__device__ __forceinline__ float sigm(float x) { return 1.f / (1.f + expf(-x)); }

__device__ __forceinline__ uint32_t smem_u32(const void* p) {
    uint32_t a;
    asm("{ .reg .u64 t; cvta.to.shared.u64 t, %1; cvt.u32.u64 %0, t; }" : "=r"(a) : "l"(p));
    return a;
}

// software grid barrier: 128 CTAs <= 148 SMs -> always co-resident
__device__ __forceinline__ void grid_sync() {
    __threadfence();
    __syncthreads();
    if (threadIdx.x == 0) {
        unsigned old = g_gen;
        unsigned t = atomicAdd(&g_count, 1);
        if (t == NCTA - 1) {
            g_count = 0;
            __threadfence();
            g_gen = old + 1;
        } else {
            while (g_gen == old) __nanosleep(20);
            __threadfence();
        }
    }
    __syncthreads();
}

// ---------------- warp-MMA helpers (compute_80-era, no arch-suffix gating) ----------
__device__ __forceinline__ void ldm4(uint32_t* r, uint32_t addr) {
    asm volatile("ldmatrix.sync.aligned.m8n8.x4.shared.b16 {%0,%1,%2,%3}, [%4];"
                 : "=r"(r[0]), "=r"(r[1]), "=r"(r[2]), "=r"(r[3]) : "r"(addr));
}

__device__ __forceinline__ void mma_bf16(float* d, const uint32_t* a, uint32_t b0, uint32_t b1) {
    asm volatile(
        "mma.sync.aligned.m16n8k16.row.col.f32.bf16.bf16.f32 "
        "{%0,%1,%2,%3}, {%4,%5,%6,%7}, {%8,%9}, {%0,%1,%2,%3};"
        : "+f"(d[0]), "+f"(d[1]), "+f"(d[2]), "+f"(d[3])
        : "r"(a[0]), "r"(a[1]), "r"(a[2]), "r"(a[3]), "r"(b0), "r"(b1));
}

__device__ __forceinline__ uint32_t pk2(float a, float b) {
    return (uint32_t)__bfloat16_as_ushort(__float2bfloat16(a)) |
           ((uint32_t)__bfloat16_as_ushort(__float2bfloat16(b)) << 16);
}

// fp32x4 -> bf16 hi (8B) + bf16 lo residual (8B)
__device__ __forceinline__ void split_store(char* hp, char* lp, float4 v) {
    float hx = __bfloat162float(__float2bfloat16(v.x));
    float hy = __bfloat162float(__float2bfloat16(v.y));
    float hz = __bfloat162float(__float2bfloat16(v.z));
    float hw = __bfloat162float(__float2bfloat16(v.w));
    uint64_t hi = (uint64_t)pk2(v.x, v.y) | ((uint64_t)pk2(v.z, v.w) << 32);
    uint64_t lo = (uint64_t)pk2(v.x - hx, v.y - hy) | ((uint64_t)pk2(v.z - hz, v.w - hw) << 32);
    *(uint64_t*)hp = hi;
    *(uint64_t*)lp = lo;
}

// -------- emb = relu(x @ W_emb^T + b_emb) --------
__global__ void emb_kernel(const float* __restrict__ x,
                           const float* __restrict__ W,
                           const float* __restrict__ bias) {
    __shared__ float ws[HH * ID];
    __shared__ float xs[8][ID];
    int tid = threadIdx.x;
    for (int i = tid; i < HH * ID; i += 256) ws[i] = W[i];
    size_t row0 = (size_t)blockIdx.x * 8;
    if (tid < 8 * ID) xs[tid / ID][tid % ID] = x[row0 * ID + tid];
    __syncthreads();
    float b = bias[tid];
#pragma unroll
    for (int r = 0; r < 8; r++) {
        float acc = b;
#pragma unroll
        for (int i = 0; i < ID; i++) acc = fmaf(xs[r][i], ws[tid * ID + i], acc);
        g_seq[(row0 + r) * HH + tid] = fmaxf(acc, 0.f);
    }
}

// ===================== tensor-core xg GEMM (validated in R10) =====================
// K chunk = 128 -> row stride RS = 136 bf16 (128 data + 8 pad)
#define RS 136
#define OFF_AHI 0
#define OFF_ALO (128 * RS * 2)               // 34816
#define OFF_BHI (2 * 128 * RS * 2)           // 69632
#define OFF_BLO (3 * 128 * RS * 2)           // 104448
#define OFF_BIAS (4 * 128 * RS * 2)          // 139264
#define XG_SMEM (OFF_BIAS + 512)             // 139776

__global__ void __launch_bounds__(256, 1) xg_mma(const float* __restrict__ wih,
                                                 const float* __restrict__ bih,
                                                 const float* __restrict__ bhh) {
    extern __shared__ char sp[];
    const uint32_t sb = smem_u32(sp);
    float* bias_s = (float*)(sp + OFF_BIAS);

    const int tid = threadIdx.x;
    const int lane = tid & 31;
    const int w = tid >> 5;
    const int wm0 = (w & 3) * 32;
    const int wn0 = (w >> 2) * 64;
    const int n0 = blockIdx.x * 128;
    const int m0 = blockIdx.y * 128;

    if (tid < 128) {
        int gc = n0 + tid;
        int wr = ((gc & 3) << 8) | (gc >> 2);
        bias_s[tid] = bih[wr] + bhh[wr];
    }

    float acc[2][8][4];
#pragma unroll
    for (int i = 0; i < 2; i++)
#pragma unroll
        for (int j = 0; j < 8; j++)
#pragma unroll
            for (int q = 0; q < 4; q++) acc[i][j][q] = 0.f;

    const int a_row = (lane & 15);
    const int a_kof = (lane >> 4) << 3;
    const int b_row = (lane & 7) + ((lane >> 4) << 3);
    const int b_kof = ((lane >> 3) & 1) << 3;

#pragma unroll
    for (int ch = 0; ch < 2; ch++) {
        const int kc0 = ch << 7;
#pragma unroll
        for (int q = 0; q < 16; q++) {
            int p = tid + (q << 8);
            int r = p >> 5;
            int k = (p & 31) << 2;
            uint32_t so = (uint32_t)(r * RS + k) * 2;
            float4 va = *(const float4*)&g_seq[(size_t)(m0 + r) * HH + kc0 + k];
            split_store(sp + OFF_AHI + so, sp + OFF_ALO + so, va);
            int gc = n0 + r;
            int wr = ((gc & 3) << 8) | (gc >> 2);
            float4 vb = *(const float4*)&wih[(size_t)wr * HH + kc0 + k];
            split_store(sp + OFF_BHI + so, sp + OFF_BLO + so, vb);
        }
        __syncthreads();

#pragma unroll
        for (int ks = 0; ks < 8; ks++) {
            const int kb = ks << 4;
            uint32_t ah[2][4], al[2][4];
#pragma unroll
            for (int mt = 0; mt < 2; mt++) {
                uint32_t off = (uint32_t)((wm0 + mt * 16 + a_row) * RS + kb + a_kof) * 2;
                ldm4(ah[mt], sb + OFF_AHI + off);
                ldm4(al[mt], sb + OFF_ALO + off);
            }
#pragma unroll
            for (int np = 0; np < 4; np++) {
                uint32_t off = (uint32_t)((wn0 + np * 16 + b_row) * RS + kb + b_kof) * 2;
                uint32_t bh[4], bl[4];
                ldm4(bh, sb + OFF_BHI + off);
                ldm4(bl, sb + OFF_BLO + off);
#pragma unroll
                for (int mt = 0; mt < 2; mt++) {
                    mma_bf16(acc[mt][np * 2], ah[mt], bh[0], bh[1]);
                    mma_bf16(acc[mt][np * 2], ah[mt], bl[0], bl[1]);
                    mma_bf16(acc[mt][np * 2], al[mt], bh[0], bh[1]);
                    mma_bf16(acc[mt][np * 2 + 1], ah[mt], bh[2], bh[3]);
                    mma_bf16(acc[mt][np * 2 + 1], ah[mt], bl[2], bl[3]);
                    mma_bf16(acc[mt][np * 2 + 1], al[mt], bh[2], bh[3]);
                }
            }
        }
        __syncthreads();
    }

    float* stg = (float*)sp;
    const int g = lane >> 2, tg = lane & 3;
#pragma unroll
    for (int mt = 0; mt < 2; mt++)
#pragma unroll
        for (int nt = 0; nt < 8; nt++) {
            int row = wm0 + mt * 16 + g;
            int col = wn0 + nt * 8 + tg * 2;
            *(float2*)&stg[row * 132 + col] = make_float2(acc[mt][nt][0], acc[mt][nt][1]);
            *(float2*)&stg[(row + 8) * 132 + col] = make_float2(acc[mt][nt][2], acc[mt][nt][3]);
        }
    __syncthreads();

#pragma unroll
    for (int q = 0; q < 16; q++) {
        int p = tid + (q << 8);
        int r = p >> 5;
        int c = (p & 31) << 2;
        float4 o = *(const float4*)&stg[r * 132 + c];
        o.x += bias_s[c + 0];
        o.y += bias_s[c + 1];
        o.z += bias_s[c + 2];
        o.w += bias_s[c + 3];
        *(float4*)&g_xg[(size_t)(m0 + r) * G4 + n0 + c] = o;
    }
}

// ============ persistent LSTM layer with tensor-core recurrence =====================
// FULL K=256 per row -> row stride LRS = 264 bf16 (256 data + 8 pad; 528B rows keep
// the 4-banks-per-row shift, ldmatrix conflict-free). THIS was the R11 bug (used 136).
#define LRS 264
#define L_WHI 0
#define L_WLO (128 * LRS * 2)                // 67584
#define L_HHI (2 * 128 * LRS * 2)            // 135168
#define L_HLO (L_HHI + 32 * LRS * 2)         // 152064
#define L_STG (L_HLO + 32 * LRS * 2)         // 168960
#define LSTM_SMEM (L_STG + 32 * 132 * 4)     // 185856  (< 227KB cap)

template <bool WRITE_Y>
__global__ void __launch_bounds__(256, 1) lstm_layer(const float* __restrict__ whh,
                                                     float* __restrict__ out_h,
                                                     float* __restrict__ out_c) {
    extern __shared__ char sp[];
    const uint32_t sb = smem_u32(sp);
    float* stg = (float*)(sp + L_STG);

    const int tid = threadIdx.x;
    const int lane = tid & 31;
    const int w = tid >> 5;
    const int jb0 = (blockIdx.x & 7) << 5;
    const int bb0 = (blockIdx.x >> 3) << 5;

    // ---- stage weights bf16 hi/lo once: row c = unit*4+gate, k-major ----
    {
        int c = tid & 127;
        int kh = (tid >> 7) << 7;
        int gate = c & 3, unit = c >> 2;
        const float* wrow = whh + (size_t)(gate * HH + jb0 + unit) * HH + kh;
#pragma unroll
        for (int q = 0; q < 32; q++) {
            float4 v = *(const float4*)(wrow + q * 4);
            uint32_t so = (uint32_t)(c * LRS + kh + q * 4) * 2;
            split_store(sp + L_WHI + so, sp + L_WLO + so, v);
        }
    }
    __syncthreads();

    const int a_row = lane & 15;
    const int a_kof = (lane >> 4) << 3;
    const int b_row = (lane & 7) + ((lane >> 4) << 3);
    const int b_kof = ((lane >> 3) & 1) << 3;
    const int wn0 = w << 4;              // this warp's 16 gate cols

    const int a4 = (tid >> 5) << 2;      // cell-update batch base
    const int jx = tid & 31;             // cell-update unit
    const int j = jb0 + jx;
    const int cb = tid >> 3;             // h-convert batch row
    const int ck = (tid & 7) << 2;       // h-convert k base

    float c_reg[4] = {0.f, 0.f, 0.f, 0.f};
    float hl[4] = {0.f, 0.f, 0.f, 0.f};

    for (int t = 0; t < SS; t++) {
        // prefetch this step's xg
        float4 xgv[4];
#pragma unroll
        for (int r = 0; r < 4; r++)
            xgv[r] = *(const float4*)&g_xg[((size_t)(bb0 + a4 + r) * SS + t) * G4 + (size_t)j * 4];

        if (t > 0) {
            // ---- convert h_prev slice [32 x 256] to bf16 hi/lo ----
            const float* hp = g_hbuf[t & 1] + (size_t)(bb0 + cb) * HH;
#pragma unroll
            for (int q = 0; q < 8; q++) {
                int k = ck + q * 32;
                float4 v = __ldcg((const float4*)(hp + k));
                uint32_t so = (uint32_t)(cb * LRS + k) * 2;
                split_store(sp + L_HHI + so, sp + L_HLO + so, v);
            }
            __syncthreads();

            // ---- warp MMA: D[32 x 16cols] over K=256, 3-term bf16 split ----
            float acc[2][2][4];
#pragma unroll
            for (int mt = 0; mt < 2; mt++)
#pragma unroll
                for (int nt = 0; nt < 2; nt++)
#pragma unroll
                    for (int q = 0; q < 4; q++) acc[mt][nt][q] = 0.f;

#pragma unroll
            for (int ks = 0; ks < 16; ks++) {
                const int kb = ks << 4;
                uint32_t ah[2][4], al[2][4], bh[4], bl[4];
#pragma unroll
                for (int mt = 0; mt < 2; mt++) {
                    uint32_t off = (uint32_t)((mt * 16 + a_row) * LRS + kb + a_kof) * 2;
                    ldm4(ah[mt], sb + L_HHI + off);
                    ldm4(al[mt], sb + L_HLO + off);
                }
                {
                    uint32_t off = (uint32_t)((wn0 + b_row) * LRS + kb + b_kof) * 2;
                    ldm4(bh, sb + L_WHI + off);
                    ldm4(bl, sb + L_WLO + off);
                }
#pragma unroll
                for (int mt = 0; mt < 2; mt++) {
                    mma_bf16(acc[mt][0], ah[mt], bh[0], bh[1]);
                    mma_bf16(acc[mt][0], ah[mt], bl[0], bl[1]);
                    mma_bf16(acc[mt][0], al[mt], bh[0], bh[1]);
                    mma_bf16(acc[mt][1], ah[mt], bh[2], bh[3]);
                    mma_bf16(acc[mt][1], ah[mt], bl[2], bl[3]);
                    mma_bf16(acc[mt][1], al[mt], bh[2], bh[3]);
                }
            }

            // ---- stage acc -> stg[32][132] ----
            int gg = lane >> 2, tg = lane & 3;
#pragma unroll
            for (int mt = 0; mt < 2; mt++)
#pragma unroll
                for (int nt = 0; nt < 2; nt++) {
                    int row = mt * 16 + gg;
                    int col = wn0 + nt * 8 + tg * 2;
                    *(float2*)&stg[row * 132 + col] = make_float2(acc[mt][nt][0], acc[mt][nt][1]);
                    *(float2*)&stg[(row + 8) * 132 + col] = make_float2(acc[mt][nt][2], acc[mt][nt][3]);
                }
            __syncthreads();
        }

        // ---- cell update ----
        float* hnext = g_hbuf[(t & 1) ^ 1];
#pragma unroll
        for (int r = 0; r < 4; r++) {
            int bl_ = a4 + r;
            float4 gv = (t > 0) ? *(const float4*)&stg[bl_ * 132 + (jx << 2)]
                                : make_float4(0.f, 0.f, 0.f, 0.f);
            float iv = sigm(gv.x + xgv[r].x);
            float fv = sigm(gv.y + xgv[r].y);
            float gt = tanhf(gv.z + xgv[r].z);
            float ov = sigm(gv.w + xgv[r].w);
            c_reg[r] = fmaf(fv, c_reg[r], iv * gt);
            float hn = ov * tanhf(c_reg[r]);
            hl[r] = hn;
            int b = bb0 + bl_;
            hnext[(size_t)b * HH + j] = hn;
            if (WRITE_Y) g_seq[((size_t)b * SS + t) * HH + j] = hn;
        }

        grid_sync();
    }

    // epilogue: final h/c from registers
#pragma unroll
    for (int r = 0; r < 4; r++) {
        size_t idx = (size_t)(bb0 + a4 + r) * HH + j;
        out_h[idx] = hl[r];
        out_c[idx] = c_reg[r];
    }
}

// -------- head: layernorm(h1) -> relu(w1) -> w2 -> mask --------
__global__ void head_kernel(const float* __restrict__ mask,
                            const float* __restrict__ ln_g, const float* __restrict__ ln_b,
                            const float* __restrict__ w1, const float* __restrict__ b1,
                            const float* __restrict__ w2, const float* __restrict__ b2,
                            float* __restrict__ out_logits) {
    int b = blockIdx.x;
    int tid = threadIdx.x;
    __shared__ float sh[HH];
    __shared__ float r1[8], r2[8];
    __shared__ float stats[2];
    __shared__ float hdn[32];

    float v = g_hbuf[0][(size_t)b * HH + tid];
    float s1 = v, s2 = v * v;
#pragma unroll
    for (int off = 16; off > 0; off >>= 1) {
        s1 += __shfl_down_sync(0xffffffffu, s1, off);
        s2 += __shfl_down_sync(0xffffffffu, s2, off);
    }
    if ((tid & 31) == 0) { r1[tid >> 5] = s1; r2[tid >> 5] = s2; }
    __syncthreads();
    if (tid == 0) {
        float t1 = 0.f, t2 = 0.f;
        for (int i = 0; i < 8; i++) { t1 += r1[i]; t2 += r2[i]; }
        float mu = t1 * (1.f / HH);
        float var = t2 * (1.f / HH) - mu * mu;
        stats[0] = mu;
        stats[1] = rsqrtf(var + 1e-5f);
    }
    __syncthreads();
    sh[tid] = (v - stats[0]) * stats[1] * ln_g[tid] + ln_b[tid];
    __syncthreads();

    int u = tid >> 3, p = tid & 7;
    float part = 0.f;
#pragma unroll
    for (int k = p; k < HH; k += 8) part = fmaf(sh[k], w1[u * HH + k], part);
    part += __shfl_down_sync(0xffffffffu, part, 4);
    part += __shfl_down_sync(0xffffffffu, part, 2);
    part += __shfl_down_sync(0xffffffffu, part, 1);
    if (p == 0) hdn[u] = fmaxf(part + b1[u], 0.f);
    __syncthreads();

    if (tid < AA) {
        float acc = b2[tid];
#pragma unroll
        for (int k = 0; k < 32; k++) acc = fmaf(hdn[k], w2[tid * 32 + k], acc);
        acc += (1.f - mask[(size_t)b * AA + tid]) * -1e9f;
        out_logits[(size_t)b * AA + tid] = acc;
    }
}

extern "C" void kernel_launch(void* const* d_in, const int* in_sizes, int n_in,
                              void* d_out, int out_size) {
    (void)in_sizes; (void)n_in; (void)out_size;
    const float* x     = (const float*)d_in[0];
    const float* mask  = (const float*)d_in[1];
    const float* W_emb = (const float*)d_in[2];
    const float* b_emb = (const float*)d_in[3];
    const float* w_ih0 = (const float*)d_in[4];
    const float* w_hh0 = (const float*)d_in[5];
    const float* b_ih0 = (const float*)d_in[6];
    const float* b_hh0 = (const float*)d_in[7];
    const float* w_ih1 = (const float*)d_in[8];
    const float* w_hh1 = (const float*)d_in[9];
    const float* b_ih1 = (const float*)d_in[10];
    const float* b_hh1 = (const float*)d_in[11];
    const float* ln_g  = (const float*)d_in[12];
    const float* ln_b  = (const float*)d_in[13];
    const float* w1    = (const float*)d_in[14];
    const float* b1    = (const float*)d_in[15];
    const float* w2    = (const float*)d_in[16];
    const float* b2    = (const float*)d_in[17];

    float* out        = (float*)d_out;
    float* out_logits = out;
    float* out_h0     = out + BB * AA;
    float* out_h1     = out_h0 + BB * HH;
    float* out_c0     = out_h1 + BB * HH;
    float* out_c1     = out_c0 + BB * HH;

    cudaFuncSetAttribute(lstm_layer<true>,
                         cudaFuncAttributeMaxDynamicSharedMemorySize, LSTM_SMEM);
    cudaFuncSetAttribute(lstm_layer<false>,
                         cudaFuncAttributeMaxDynamicSharedMemorySize, LSTM_SMEM);
    cudaFuncSetAttribute(xg_mma,
                         cudaFuncAttributeMaxDynamicSharedMemorySize, XG_SMEM);

    dim3 xg_grid(G4 / 128, (BB * SS) / 128);   // (8, 1024)

    emb_kernel<<<(BB * SS) / 8, 256>>>(x, W_emb, b_emb);

    // layer 0
    xg_mma<<<xg_grid, 256, XG_SMEM>>>(w_ih0, b_ih0, b_hh0);
    lstm_layer<true><<<NCTA, 256, LSTM_SMEM>>>(w_hh0, out_h0, out_c0);

    // layer 1 (y0 in g_seq)
    xg_mma<<<xg_grid, 256, XG_SMEM>>>(w_ih1, b_ih1, b_hh1);
    lstm_layer<false><<<NCTA, 256, LSTM_SMEM>>>(w_hh1, out_h1, out_c1);

    // head: last == final h1 (in g_hbuf[0])
    head_kernel<<<BB, 256>>>(mask, ln_g, ln_b, w1, b1, w2, b2, out_logits);
}

// round 13
// speedup vs baseline: 2.5732x; 1.0390x over previous
#include <cuda_runtime.h>
#include <cuda_bf16.h>
#include <math.h>
#include <stdint.h>

#define BB 512
#define SS 256
#define ID 12
#define HH 256
#define AA 9
#define G4 1024   // 4*HH
#define NCTA 128

// -------- scratch (static device allocations; no runtime alloc) --------
static __device__ float g_seq[(size_t)BB * SS * HH];   // emb, then reused as y0
static __device__ float g_xg[(size_t)BB * SS * G4];    // input gates, cols gc = j*4+gate
static __device__ float g_hbuf[2][BB * HH];            // ping-pong hidden state
// per-batch-group barriers: 16 groups of 8 CTAs; 128B stride kills L2-line contention
static __device__ unsigned g_cnt2[16 * 32];
static __device__ volatile unsigned g_gen2[16 * 32];

__device__ __forceinline__ float sigm(float x) { return 1.f / (1.f + expf(-x)); }

__device__ __forceinline__ uint32_t smem_u32(const void* p) {
    uint32_t a;
    asm("{ .reg .u64 t; cvta.to.shared.u64 t, %1; cvt.u32.u64 %0, t; }" : "=r"(a) : "l"(p));
    return a;
}

// 8-CTA batch-group barrier (h for group bb is produced and consumed only within group bb)
__device__ __forceinline__ void group_sync(int grp) {
    __threadfence();
    __syncthreads();
    if (threadIdx.x == 0) {
        int gi = grp * 32;
        unsigned old = g_gen2[gi];
        if (atomicAdd(&g_cnt2[gi], 1u) == 7u) {
            g_cnt2[gi] = 0;
            __threadfence();
            g_gen2[gi] = old + 1;
        } else {
            while (g_gen2[gi] == old) __nanosleep(20);
            __threadfence();
        }
    }
    __syncthreads();
}

// ---------------- warp-MMA helpers (compute_80-era, no arch-suffix gating) ----------
__device__ __forceinline__ void ldm4(uint32_t* r, uint32_t addr) {
    asm volatile("ldmatrix.sync.aligned.m8n8.x4.shared.b16 {%0,%1,%2,%3}, [%4];"
                 : "=r"(r[0]), "=r"(r[1]), "=r"(r[2]), "=r"(r[3]) : "r"(addr));
}

__device__ __forceinline__ void mma_bf16(float* d, const uint32_t* a, uint32_t b0, uint32_t b1) {
    asm volatile(
        "mma.sync.aligned.m16n8k16.row.col.f32.bf16.bf16.f32 "
        "{%0,%1,%2,%3}, {%4,%5,%6,%7}, {%8,%9}, {%0,%1,%2,%3};"
        : "+f"(d[0]), "+f"(d[1]), "+f"(d[2]), "+f"(d[3])
        : "r"(a[0]), "r"(a[1]), "r"(a[2]), "r"(a[3]), "r"(b0), "r"(b1));
}

__device__ __forceinline__ uint32_t pk2(float a, float b) {
    return (uint32_t)__bfloat16_as_ushort(__float2bfloat16(a)) |
           ((uint32_t)__bfloat16_as_ushort(__float2bfloat16(b)) << 16);
}

// fp32x4 -> bf16 hi (8B) + bf16 lo residual (8B)
__device__ __forceinline__ void split_store(char* hp, char* lp, float4 v) {
    float hx = __bfloat162float(__float2bfloat16(v.x));
    float hy = __bfloat162float(__float2bfloat16(v.y));
    float hz = __bfloat162float(__float2bfloat16(v.z));
    float hw = __bfloat162float(__float2bfloat16(v.w));
    uint64_t hi = (uint64_t)pk2(v.x, v.y) | ((uint64_t)pk2(v.z, v.w) << 32);
    uint64_t lo = (uint64_t)pk2(v.x - hx, v.y - hy) | ((uint64_t)pk2(v.z - hz, v.w - hw) << 32);
    *(uint64_t*)hp = hi;
    *(uint64_t*)lp = lo;
}

// -------- emb = relu(x @ W_emb^T + b_emb) --------
__global__ void emb_kernel(const float* __restrict__ x,
                           const float* __restrict__ W,
                           const float* __restrict__ bias) {
    __shared__ float ws[HH * ID];
    __shared__ float xs[8][ID];
    int tid = threadIdx.x;
    for (int i = tid; i < HH * ID; i += 256) ws[i] = W[i];
    size_t row0 = (size_t)blockIdx.x * 8;
    if (tid < 8 * ID) xs[tid / ID][tid % ID] = x[row0 * ID + tid];
    __syncthreads();
    float b = bias[tid];
#pragma unroll
    for (int r = 0; r < 8; r++) {
        float acc = b;
#pragma unroll
        for (int i = 0; i < ID; i++) acc = fmaf(xs[r][i], ws[tid * ID + i], acc);
        g_seq[(row0 + r) * HH + tid] = fmaxf(acc, 0.f);
    }
}

// ===================== tensor-core xg GEMM: 512 threads, warp tile 32x32 ============
// K chunk = 128 -> row stride RS = 136 bf16 (128 data + 8 pad)
#define RS 136
#define OFF_AHI 0
#define OFF_ALO (128 * RS * 2)               // 34816
#define OFF_BHI (2 * 128 * RS * 2)           // 69632
#define OFF_BLO (3 * 128 * RS * 2)           // 104448
#define OFF_BIAS (4 * 128 * RS * 2)          // 139264
#define XG_SMEM (OFF_BIAS + 512)             // 139776

__global__ void __launch_bounds__(512, 1) xg_mma(const float* __restrict__ wih,
                                                 const float* __restrict__ bih,
                                                 const float* __restrict__ bhh) {
    extern __shared__ char sp[];
    const uint32_t sb = smem_u32(sp);
    float* bias_s = (float*)(sp + OFF_BIAS);

    const int tid = threadIdx.x;
    const int lane = tid & 31;
    const int w = tid >> 5;                  // 0..15
    const int wm0 = (w & 3) * 32;            // 4 m-slices
    const int wn0 = (w >> 2) * 32;           // 4 n-slices
    const int n0 = blockIdx.x * 128;
    const int m0 = blockIdx.y * 128;

    if (tid < 128) {
        int gc = n0 + tid;
        int wr = ((gc & 3) << 8) | (gc >> 2);
        bias_s[tid] = bih[wr] + bhh[wr];
    }

    float acc[2][4][4];
#pragma unroll
    for (int i = 0; i < 2; i++)
#pragma unroll
        for (int j = 0; j < 4; j++)
#pragma unroll
            for (int q = 0; q < 4; q++) acc[i][j][q] = 0.f;

    const int a_row = (lane & 15);
    const int a_kof = (lane >> 4) << 3;
    const int b_row = (lane & 7) + ((lane >> 4) << 3);
    const int b_kof = ((lane >> 3) & 1) << 3;

#pragma unroll
    for (int ch = 0; ch < 2; ch++) {
        const int kc0 = ch << 7;
        // ---- load fp32, split bf16 hi/lo into smem (8 positions per thread) ----
#pragma unroll
        for (int q = 0; q < 8; q++) {
            int p = tid + (q << 9);
            int r = p >> 5;
            int k = (p & 31) << 2;
            uint32_t so = (uint32_t)(r * RS + k) * 2;
            float4 va = *(const float4*)&g_seq[(size_t)(m0 + r) * HH + kc0 + k];
            split_store(sp + OFF_AHI + so, sp + OFF_ALO + so, va);
            int gc = n0 + r;
            int wr = ((gc & 3) << 8) | (gc >> 2);
            float4 vb = *(const float4*)&wih[(size_t)wr * HH + kc0 + k];
            split_store(sp + OFF_BHI + so, sp + OFF_BLO + so, vb);
        }
        __syncthreads();

#pragma unroll
        for (int ks = 0; ks < 8; ks++) {
            const int kb = ks << 4;
            uint32_t ah[2][4], al[2][4];
#pragma unroll
            for (int mt = 0; mt < 2; mt++) {
                uint32_t off = (uint32_t)((wm0 + mt * 16 + a_row) * RS + kb + a_kof) * 2;
                ldm4(ah[mt], sb + OFF_AHI + off);
                ldm4(al[mt], sb + OFF_ALO + off);
            }
#pragma unroll
            for (int np = 0; np < 2; np++) {
                uint32_t off = (uint32_t)((wn0 + np * 16 + b_row) * RS + kb + b_kof) * 2;
                uint32_t bh[4], bl[4];
                ldm4(bh, sb + OFF_BHI + off);
                ldm4(bl, sb + OFF_BLO + off);
#pragma unroll
                for (int mt = 0; mt < 2; mt++) {
                    mma_bf16(acc[mt][np * 2], ah[mt], bh[0], bh[1]);
                    mma_bf16(acc[mt][np * 2], ah[mt], bl[0], bl[1]);
                    mma_bf16(acc[mt][np * 2], al[mt], bh[0], bh[1]);
                    mma_bf16(acc[mt][np * 2 + 1], ah[mt], bh[2], bh[3]);
                    mma_bf16(acc[mt][np * 2 + 1], ah[mt], bl[2], bl[3]);
                    mma_bf16(acc[mt][np * 2 + 1], al[mt], bh[2], bh[3]);
                }
            }
        }
        __syncthreads();
    }

    // ---- epilogue: stage acc in smem (reuses Ahi/Alo region), coalesced out ----
    float* stg = (float*)sp;                 // [128][132] floats = 67,584 B <= 69,632
    const int g = lane >> 2, tg = lane & 3;
#pragma unroll
    for (int mt = 0; mt < 2; mt++)
#pragma unroll
        for (int nt = 0; nt < 4; nt++) {
            int row = wm0 + mt * 16 + g;
            int col = wn0 + nt * 8 + tg * 2;
            *(float2*)&stg[row * 132 + col] = make_float2(acc[mt][nt][0], acc[mt][nt][1]);
            *(float2*)&stg[(row + 8) * 132 + col] = make_float2(acc[mt][nt][2], acc[mt][nt][3]);
        }
    __syncthreads();

#pragma unroll
    for (int q = 0; q < 8; q++) {
        int p = tid + (q << 9);
        int r = p >> 5;
        int c = (p & 31) << 2;
        float4 o = *(const float4*)&stg[r * 132 + c];
        o.x += bias_s[c + 0];
        o.y += bias_s[c + 1];
        o.z += bias_s[c + 2];
        o.w += bias_s[c + 3];
        *(float4*)&g_xg[(size_t)(m0 + r) * G4 + n0 + c] = o;
    }
}

// ============ persistent LSTM layer with tensor-core recurrence =====================
// FULL K=256 per row -> row stride LRS = 264 bf16 (256 data + 8 pad)
#define LRS 264
#define L_WHI 0
#define L_WLO (128 * LRS * 2)                // 67584
#define L_HHI (2 * 128 * LRS * 2)            // 135168
#define L_HLO (L_HHI + 32 * LRS * 2)         // 152064
#define L_STG (L_HLO + 32 * LRS * 2)         // 168960
#define LSTM_SMEM (L_STG + 32 * 132 * 4)     // 185856  (< 227KB cap)

template <bool WRITE_Y>
__global__ void __launch_bounds__(256, 1) lstm_layer(const float* __restrict__ whh,
                                                     float* __restrict__ out_h,
                                                     float* __restrict__ out_c) {
    extern __shared__ char sp[];
    const uint32_t sb = smem_u32(sp);
    float* stg = (float*)(sp + L_STG);

    const int tid = threadIdx.x;
    const int lane = tid & 31;
    const int w = tid >> 5;
    const int jb0 = (blockIdx.x & 7) << 5;
    const int grp = blockIdx.x >> 3;         // batch group = barrier group
    const int bb0 = grp << 5;

    // ---- stage weights bf16 hi/lo once: row c = unit*4+gate, k-major ----
    {
        int c = tid & 127;
        int kh = (tid >> 7) << 7;
        int gate = c & 3, unit = c >> 2;
        const float* wrow = whh + (size_t)(gate * HH + jb0 + unit) * HH + kh;
#pragma unroll
        for (int q = 0; q < 32; q++) {
            float4 v = *(const float4*)(wrow + q * 4);
            uint32_t so = (uint32_t)(c * LRS + kh + q * 4) * 2;
            split_store(sp + L_WHI + so, sp + L_WLO + so, v);
        }
    }
    __syncthreads();

    const int a_row = lane & 15;
    const int a_kof = (lane >> 4) << 3;
    const int b_row = (lane & 7) + ((lane >> 4) << 3);
    const int b_kof = ((lane >> 3) & 1) << 3;
    const int wn0 = w << 4;              // this warp's 16 gate cols

    const int a4 = (tid >> 5) << 2;      // cell-update batch base
    const int jx = tid & 31;             // cell-update unit
    const int j = jb0 + jx;
    const int cb = tid >> 3;             // h-convert batch row
    const int ck = (tid & 7) << 2;       // h-convert k base

    float c_reg[4] = {0.f, 0.f, 0.f, 0.f};
    float hl[4] = {0.f, 0.f, 0.f, 0.f};

    for (int t = 0; t < SS; t++) {
        // prefetch this step's xg
        float4 xgv[4];
#pragma unroll
        for (int r = 0; r < 4; r++)
            xgv[r] = *(const float4*)&g_xg[((size_t)(bb0 + a4 + r) * SS + t) * G4 + (size_t)j * 4];

        if (t > 0) {
            // ---- convert h_prev slice [32 x 256] to bf16 hi/lo ----
            const float* hp = g_hbuf[t & 1] + (size_t)(bb0 + cb) * HH;
#pragma unroll
            for (int q = 0; q < 8; q++) {
                int k = ck + q * 32;
                float4 v = __ldcg((const float4*)(hp + k));
                uint32_t so = (uint32_t)(cb * LRS + k) * 2;
                split_store(sp + L_HHI + so, sp + L_HLO + so, v);
            }
            __syncthreads();

            // ---- warp MMA: D[32 x 16cols] over K=256, 3-term bf16 split ----
            float acc[2][2][4];
#pragma unroll
            for (int mt = 0; mt < 2; mt++)
#pragma unroll
                for (int nt = 0; nt < 2; nt++)
#pragma unroll
                    for (int q = 0; q < 4; q++) acc[mt][nt][q] = 0.f;

#pragma unroll
            for (int ks = 0; ks < 16; ks++) {
                const int kb = ks << 4;
                uint32_t ah[2][4], al[2][4], bh[4], bl[4];
#pragma unroll
                for (int mt = 0; mt < 2; mt++) {
                    uint32_t off = (uint32_t)((mt * 16 + a_row) * LRS + kb + a_kof) * 2;
                    ldm4(ah[mt], sb + L_HHI + off);
                    ldm4(al[mt], sb + L_HLO + off);
                }
                {
                    uint32_t off = (uint32_t)((wn0 + b_row) * LRS + kb + b_kof) * 2;
                    ldm4(bh, sb + L_WHI + off);
                    ldm4(bl, sb + L_WLO + off);
                }
#pragma unroll
                for (int mt = 0; mt < 2; mt++) {
                    mma_bf16(acc[mt][0], ah[mt], bh[0], bh[1]);
                    mma_bf16(acc[mt][0], ah[mt], bl[0], bl[1]);
                    mma_bf16(acc[mt][0], al[mt], bh[0], bh[1]);
                    mma_bf16(acc[mt][1], ah[mt], bh[2], bh[3]);
                    mma_bf16(acc[mt][1], ah[mt], bl[2], bl[3]);
                    mma_bf16(acc[mt][1], al[mt], bh[2], bh[3]);
                }
            }

            // ---- stage acc -> stg[32][132] ----
            int gg = lane >> 2, tg = lane & 3;
#pragma unroll
            for (int mt = 0; mt < 2; mt++)
#pragma unroll
                for (int nt = 0; nt < 2; nt++) {
                    int row = mt * 16 + gg;
                    int col = wn0 + nt * 8 + tg * 2;
                    *(float2*)&stg[row * 132 + col] = make_float2(acc[mt][nt][0], acc[mt][nt][1]);
                    *(float2*)&stg[(row + 8) * 132 + col] = make_float2(acc[mt][nt][2], acc[mt][nt][3]);
                }
            __syncthreads();
        }

        // ---- cell update ----
        float* hnext = g_hbuf[(t & 1) ^ 1];
#pragma unroll
        for (int r = 0; r < 4; r++) {
            int bl_ = a4 + r;
            float4 gv = (t > 0) ? *(const float4*)&stg[bl_ * 132 + (jx << 2)]
                                : make_float4(0.f, 0.f, 0.f, 0.f);
            float iv = sigm(gv.x + xgv[r].x);
            float fv = sigm(gv.y + xgv[r].y);
            float gt = tanhf(gv.z + xgv[r].z);
            float ov = sigm(gv.w + xgv[r].w);
            c_reg[r] = fmaf(fv, c_reg[r], iv * gt);
            float hn = ov * tanhf(c_reg[r]);
            hl[r] = hn;
            int b = bb0 + bl_;
            hnext[(size_t)b * HH + j] = hn;
            if (WRITE_Y) g_seq[((size_t)b * SS + t) * HH + j] = hn;
        }

        group_sync(grp);   // only the 8 CTAs of this batch group exchange h
    }

    // epilogue: final h/c from registers
#pragma unroll
    for (int r = 0; r < 4; r++) {
        size_t idx = (size_t)(bb0 + a4 + r) * HH + j;
        out_h[idx] = hl[r];
        out_c[idx] = c_reg[r];
    }
}

// -------- head: layernorm(h1) -> relu(w1) -> w2 -> mask --------
__global__ void head_kernel(const float* __restrict__ mask,
                            const float* __restrict__ ln_g, const float* __restrict__ ln_b,
                            const float* __restrict__ w1, const float* __restrict__ b1,
                            const float* __restrict__ w2, const float* __restrict__ b2,
                            float* __restrict__ out_logits) {
    int b = blockIdx.x;
    int tid = threadIdx.x;
    __shared__ float sh[HH];
    __shared__ float r1[8], r2[8];
    __shared__ float stats[2];
    __shared__ float hdn[32];

    float v = g_hbuf[0][(size_t)b * HH + tid];
    float s1 = v, s2 = v * v;
#pragma unroll
    for (int off = 16; off > 0; off >>= 1) {
        s1 += __shfl_down_sync(0xffffffffu, s1, off);
        s2 += __shfl_down_sync(0xffffffffu, s2, off);
    }
    if ((tid & 31) == 0) { r1[tid >> 5] = s1; r2[tid >> 5] = s2; }
    __syncthreads();
    if (tid == 0) {
        float t1 = 0.f, t2 = 0.f;
        for (int i = 0; i < 8; i++) { t1 += r1[i]; t2 += r2[i]; }
        float mu = t1 * (1.f / HH);
        float var = t2 * (1.f / HH) - mu * mu;
        stats[0] = mu;
        stats[1] = rsqrtf(var + 1e-5f);
    }
    __syncthreads();
    sh[tid] = (v - stats[0]) * stats[1] * ln_g[tid] + ln_b[tid];
    __syncthreads();

    int u = tid >> 3, p = tid & 7;
    float part = 0.f;
#pragma unroll
    for (int k = p; k < HH; k += 8) part = fmaf(sh[k], w1[u * HH + k], part);
    part += __shfl_down_sync(0xffffffffu, part, 4);
    part += __shfl_down_sync(0xffffffffu, part, 2);
    part += __shfl_down_sync(0xffffffffu, part, 1);
    if (p == 0) hdn[u] = fmaxf(part + b1[u], 0.f);
    __syncthreads();

    if (tid < AA) {
        float acc = b2[tid];
#pragma unroll
        for (int k = 0; k < 32; k++) acc = fmaf(hdn[k], w2[tid * 32 + k], acc);
        acc += (1.f - mask[(size_t)b * AA + tid]) * -1e9f;
        out_logits[(size_t)b * AA + tid] = acc;
    }
}

extern "C" void kernel_launch(void* const* d_in, const int* in_sizes, int n_in,
                              void* d_out, int out_size) {
    (void)in_sizes; (void)n_in; (void)out_size;
    const float* x     = (const float*)d_in[0];
    const float* mask  = (const float*)d_in[1];
    const float* W_emb = (const float*)d_in[2];
    const float* b_emb = (const float*)d_in[3];
    const float* w_ih0 = (const float*)d_in[4];
    const float* w_hh0 = (const float*)d_in[5];
    const float* b_ih0 = (const float*)d_in[6];
    const float* b_hh0 = (const float*)d_in[7];
    const float* w_ih1 = (const float*)d_in[8];
    const float* w_hh1 = (const float*)d_in[9];
    const float* b_ih1 = (const float*)d_in[10];
    const float* b_hh1 = (const float*)d_in[11];
    const float* ln_g  = (const float*)d_in[12];
    const float* ln_b  = (const float*)d_in[13];
    const float* w1    = (const float*)d_in[14];
    const float* b1    = (const float*)d_in[15];
    const float* w2    = (const float*)d_in[16];
    const float* b2    = (const float*)d_in[17];

    float* out        = (float*)d_out;
    float* out_logits = out;
    float* out_h0     = out + BB * AA;
    float* out_h1     = out_h0 + BB * HH;
    float* out_c0     = out_h1 + BB * HH;
    float* out_c1     = out_c0 + BB * HH;

    cudaFuncSetAttribute(lstm_layer<true>,
                         cudaFuncAttributeMaxDynamicSharedMemorySize, LSTM_SMEM);
    cudaFuncSetAttribute(lstm_layer<false>,
                         cudaFuncAttributeMaxDynamicSharedMemorySize, LSTM_SMEM);
    cudaFuncSetAttribute(xg_mma,
                         cudaFuncAttributeMaxDynamicSharedMemorySize, XG_SMEM);

    dim3 xg_grid(G4 / 128, (BB * SS) / 128);   // (8, 1024)

    emb_kernel<<<(BB * SS) / 8, 256>>>(x, W_emb, b_emb);

    // layer 0
    xg_mma<<<xg_grid, 512, XG_SMEM>>>(w_ih0, b_ih0, b_hh0);
    lstm_layer<true><<<NCTA, 256, LSTM_SMEM>>>(w_hh0, out_h0, out_c0);

    // layer 1 (y0 in g_seq)
    xg_mma<<<xg_grid, 512, XG_SMEM>>>(w_ih1, b_ih1, b_hh1);
    lstm_layer<false><<<NCTA, 256, LSTM_SMEM>>>(w_hh1, out_h1, out_c1);

    // head: last == final h1 (in g_hbuf[0])
    head_kernel<<<BB, 256>>>(mask, ln_g, ln_b, w1, b1, w2, b2, out_logits);
}